// round 8
// baseline (speedup 1.0000x reference)
#include <cuda_runtime.h>
#include <cuda_bf16.h>
#include <math.h>
#include <stdint.h>

#define T_STEPS 128
#define B_ENV   256
#define N_TOT   (T_STEPS * B_ENV)   // 32768
#define HID     128
#define NFLAT   1024
#define NG      512                  // 4*HID

// -------- scratch (static device arrays; no allocation) --------
__device__ float g_gatex[N_TOT * NG];            // 64 MB
__device__ float g_whhT [HID * NG];              // 256 KB
__device__ float g_hid  [N_TOT * HID];           // 16 MB
__device__ __nv_bfloat16 g_featH[N_TOT * NFLAT]; // 64 MB
__device__ __nv_bfloat16 g_featL[N_TOT * NFLAT]; // 64 MB
__device__ __nv_bfloat16 g_wihH [NG * NFLAT];    // 1 MB
__device__ __nv_bfloat16 g_wihL [NG * NFLAT];    // 1 MB

// ================= helpers =================
typedef unsigned long long F32X2;
__device__ __forceinline__ F32X2 pk2(float lo, float hi) {
    F32X2 r;
    asm("mov.b64 %0, {%1, %2};" : "=l"(r) : "f"(lo), "f"(hi));
    return r;
}
__device__ __forceinline__ void upk2(float& lo, float& hi, F32X2 v) {
    asm("mov.b64 {%0, %1}, %2;" : "=f"(lo), "=f"(hi) : "l"(v));
}
__device__ __forceinline__ void fma2(F32X2& d, F32X2 a, F32X2 b) {
    asm("fma.rn.f32x2 %0, %1, %2, %0;" : "+l"(d) : "l"(a), "l"(b));
}
__device__ __forceinline__ uint32_t s2u(const void* p) {
    uint32_t a;
    asm("{ .reg .u64 t; cvta.to.shared.u64 t, %1; cvt.u32.u64 %0, t; }"
        : "=r"(a) : "l"(p));
    return a;
}
__device__ __forceinline__ void ldsm4(uint32_t* r, uint32_t addr) {
    asm volatile("ldmatrix.sync.aligned.m8n8.x4.shared.b16 {%0,%1,%2,%3}, [%4];"
                 : "=r"(r[0]), "=r"(r[1]), "=r"(r[2]), "=r"(r[3]) : "r"(addr));
}
__device__ __forceinline__ void mma16816(float* d, const uint32_t* a, const uint32_t* b) {
    asm volatile(
        "mma.sync.aligned.m16n8k16.row.col.f32.bf16.bf16.f32 "
        "{%0,%1,%2,%3}, {%4,%5,%6,%7}, {%8,%9}, {%0,%1,%2,%3};"
        : "+f"(d[0]), "+f"(d[1]), "+f"(d[2]), "+f"(d[3])
        : "r"(a[0]), "r"(a[1]), "r"(a[2]), "r"(a[3]), "r"(b[0]), "r"(b[1]));
}
#define CPA16(dst, src) \
    asm volatile("cp.async.cg.shared.global [%0], [%1], 16;" :: "r"(dst), "l"(src))

// ============================================================
// Kernel 0a: transpose w_hh [512,128] -> w_hhT [128,512]
// ============================================================
__global__ void k_transpose_whh(const float* __restrict__ whh) {
    int idx = blockIdx.x * blockDim.x + threadIdx.x;
    if (idx < NG * HID) {
        int k = idx >> 9;
        int j = idx & 511;
        g_whhT[idx] = whh[j * HID + k];
    }
}

// ============================================================
// Kernel 0b: split w_ih into bf16 hi/lo
// ============================================================
__global__ void k_split_wih(const float* __restrict__ wih) {
    int idx = blockIdx.x * blockDim.x + threadIdx.x;
    if (idx < NG * NFLAT) {
        float v = wih[idx];
        __nv_bfloat16 h = __float2bfloat16(v);
        g_wihH[idx] = h;
        g_wihL[idx] = __float2bfloat16(v - __bfloat162float(h));
    }
}

// ============================================================
// Kernel 1: fused conv stack, register-blocked + f32x2 packed FMA.
// One sample per warp; channel pairs packed into f32x2 lanes.
// ============================================================
#define CONV_WSM 10544
#define CONV_PW  1523

__global__ void __launch_bounds__(256)
k_conv(const float* __restrict__ obs,
       const float* __restrict__ w1, const float* __restrict__ b1,
       const float* __restrict__ w2, const float* __restrict__ b2,
       const float* __restrict__ w3, const float* __restrict__ b3) {
    extern __shared__ float sm[];
    float* W1 = sm;
    float* B1 = sm + 192;
    float* W2 = sm + 208;
    float* B2 = sm + 2256;
    float* W3 = sm + 2288;
    float* B3 = sm + 10480;
    int tid = threadIdx.x;
    for (int i = tid; i < 192;  i += 256) W1[i] = w1[i];
    for (int i = tid; i < 16;   i += 256) B1[i] = b1[i];
    for (int i = tid; i < 2048; i += 256) W2[i] = w2[i];
    for (int i = tid; i < 32;   i += 256) B2[i] = b2[i];
    for (int i = tid; i < 8192; i += 256) W3[i] = w3[i];
    for (int i = tid; i < 64;   i += 256) B3[i] = b3[i];
    __syncthreads();

    int warp = tid >> 5, lane = tid & 31;
    int n = blockIdx.x * 8 + warp;
    float* buf = sm + CONV_WSM + warp * CONV_PW;
    float* O  = buf;          // obs [7][7][3] HWC
    float* X1 = buf + 147;    // [16][6][6]
    float* X2 = buf + 723;    // [32][5][5]

    const float* op = obs + (size_t)n * 147;
    for (int i = lane; i < 147; i += 32) O[i] = op[i];
    __syncwarp();

    // ---- conv1: lane = (ch, row-half), scalar (small) ----
    {
        int ch = lane >> 1, half = lane & 1, y0 = half * 3;
        float acc[3][6];
        float bv = B1[ch];
        #pragma unroll
        for (int r = 0; r < 3; r++)
            #pragma unroll
            for (int x = 0; x < 6; x++) acc[r][x] = bv;
        for (int ci = 0; ci < 3; ci++) {
            const float* w = W1 + ch * 12 + ci * 4;
            float w0 = w[0], w1v = w[1], w2v = w[2], w3v = w[3];
            float in[4][7];
            #pragma unroll
            for (int r = 0; r < 4; r++)
                #pragma unroll
                for (int x = 0; x < 7; x++)
                    in[r][x] = O[((y0 + r) * 7 + x) * 3 + ci];
            #pragma unroll
            for (int r = 0; r < 3; r++)
                #pragma unroll
                for (int x = 0; x < 6; x++)
                    acc[r][x] += in[r][x] * w0 + in[r][x + 1] * w1v
                               + in[r + 1][x] * w2v + in[r + 1][x + 1] * w3v;
        }
        #pragma unroll
        for (int r = 0; r < 3; r++)
            #pragma unroll
            for (int x = 0; x < 6; x++)
                X1[ch * 36 + (y0 + r) * 6 + x] = fmaxf(acc[r][x], 0.f);
    }
    __syncwarp();

    // ---- conv2: lane = (ch-pair, row-half). f32x2 packs (ch, ch+16) ----
    {
        int chp = lane & 15, halfc = lane >> 4;
        int ca = chp, cb = chp + 16;
        int y0out = halfc * 3;          // out rows y0out.. (3 rows half0, 2 half1)
        F32X2 acc2[3][5];
        F32X2 binit = pk2(B2[ca], B2[cb]);
        #pragma unroll
        for (int r = 0; r < 3; r++)
            #pragma unroll
            for (int x = 0; x < 5; x++) acc2[r][x] = binit;
        for (int ci = 0; ci < 16; ci++) {
            const float* wa = W2 + ca * 64 + ci * 4;
            const float* wb = W2 + cb * 64 + ci * 4;
            F32X2 w20 = pk2(wa[0], wb[0]), w21 = pk2(wa[1], wb[1]);
            F32X2 w22 = pk2(wa[2], wb[2]), w23 = pk2(wa[3], wb[3]);
            F32X2 in2[4][6];
            const float* xp = X1 + ci * 36;
            #pragma unroll
            for (int r = 0; r < 4; r++) {
                int ir = y0out + r; if (ir > 5) ir = 5;   // half1 r=3 unused
                #pragma unroll
                for (int x = 0; x < 6; x++) {
                    float v = xp[ir * 6 + x];
                    in2[r][x] = pk2(v, v);
                }
            }
            #pragma unroll
            for (int r = 0; r < 3; r++) {
                if (r < 3 - halfc) {
                    #pragma unroll
                    for (int x = 0; x < 5; x++) {
                        fma2(acc2[r][x], in2[r][x],     w20);
                        fma2(acc2[r][x], in2[r][x + 1], w21);
                        fma2(acc2[r][x], in2[r + 1][x],     w22);
                        fma2(acc2[r][x], in2[r + 1][x + 1], w23);
                    }
                }
            }
        }
        #pragma unroll
        for (int r = 0; r < 3; r++) {
            if (r < 3 - halfc) {
                #pragma unroll
                for (int x = 0; x < 5; x++) {
                    float va, vb;
                    upk2(va, vb, acc2[r][x]);
                    X2[ca * 25 + (y0out + r) * 5 + x] = fmaxf(va, 0.f);
                    X2[cb * 25 + (y0out + r) * 5 + x] = fmaxf(vb, 0.f);
                }
            }
        }
    }
    __syncwarp();

    // ---- conv3: lane owns channels (lane, lane+32), f32x2 packed ----
    {
        int ca = lane, cb = lane + 32;
        F32X2 acc2[4][4];
        F32X2 binit = pk2(B3[ca], B3[cb]);
        #pragma unroll
        for (int y = 0; y < 4; y++)
            #pragma unroll
            for (int x = 0; x < 4; x++) acc2[y][x] = binit;
        for (int ci = 0; ci < 32; ci++) {
            const float* wa = W3 + ca * 128 + ci * 4;
            const float* wb = W3 + cb * 128 + ci * 4;
            F32X2 w20 = pk2(wa[0], wb[0]), w21 = pk2(wa[1], wb[1]);
            F32X2 w22 = pk2(wa[2], wb[2]), w23 = pk2(wa[3], wb[3]);
            F32X2 in2[5][5];
            const float* xp = X2 + ci * 25;
            #pragma unroll
            for (int y = 0; y < 5; y++)
                #pragma unroll
                for (int x = 0; x < 5; x++) {
                    float v = xp[y * 5 + x];
                    in2[y][x] = pk2(v, v);
                }
            #pragma unroll
            for (int y = 0; y < 4; y++)
                #pragma unroll
                for (int x = 0; x < 4; x++) {
                    fma2(acc2[y][x], in2[y][x],     w20);
                    fma2(acc2[y][x], in2[y][x + 1], w21);
                    fma2(acc2[y][x], in2[y + 1][x],     w22);
                    fma2(acc2[y][x], in2[y + 1][x + 1], w23);
                }
        }
        float a0[4][4], a1[4][4];
        #pragma unroll
        for (int y = 0; y < 4; y++)
            #pragma unroll
            for (int x = 0; x < 4; x++) upk2(a0[y][x], a1[y][x], acc2[y][x]);

        __nv_bfloat162* ohA = (__nv_bfloat162*)(g_featH + (size_t)n * NFLAT + ca * 16);
        __nv_bfloat162* olA = (__nv_bfloat162*)(g_featL + (size_t)n * NFLAT + ca * 16);
        __nv_bfloat162* ohB = (__nv_bfloat162*)(g_featH + (size_t)n * NFLAT + cb * 16);
        __nv_bfloat162* olB = (__nv_bfloat162*)(g_featL + (size_t)n * NFLAT + cb * 16);
        #pragma unroll
        for (int q = 0; q < 8; q++) {
            int y = q >> 1, x = (q & 1) * 2;
            float v0 = fmaxf(a0[y][x], 0.f), v1 = fmaxf(a0[y][x + 1], 0.f);
            __nv_bfloat16 h0v = __float2bfloat16(v0), h1v = __float2bfloat16(v1);
            ohA[q] = __nv_bfloat162(h0v, h1v);
            olA[q] = __nv_bfloat162(
                __float2bfloat16(v0 - __bfloat162float(h0v)),
                __float2bfloat16(v1 - __bfloat162float(h1v)));
            float u0 = fmaxf(a1[y][x], 0.f), u1 = fmaxf(a1[y][x + 1], 0.f);
            __nv_bfloat16 g0v = __float2bfloat16(u0), g1v = __float2bfloat16(u1);
            ohB[q] = __nv_bfloat162(g0v, g1v);
            olB[q] = __nv_bfloat162(
                __float2bfloat16(u0 - __bfloat162float(g0v)),
                __float2bfloat16(u1 - __bfloat162float(g1v)));
        }
    }
}

// ============================================================
// Kernel 2: split-bf16 GEMM via mma.sync, BK=64, product-outer order.
// grid = (8 col-blocks, 256 row-blocks) for L2 reuse of A.
// ============================================================
#define RS2 144                      // row stride bytes (64 bf16 -> 128B + pad)
#define G2_AH(buf) (256 + (buf) * 55296)
#define G2_AL(buf) (G2_AH(buf) + 18432)
#define G2_BH(buf) (G2_AH(buf) + 36864)
#define G2_BL(buf) (G2_AH(buf) + 46080)
#define G2_TOT (256 + 2 * 55296)     // 110848 bytes

__global__ void __launch_bounds__(256, 2)
k_gemm_mma(const float* __restrict__ bih, const float* __restrict__ bhh) {
    extern __shared__ char smc[];
    uint32_t sb = s2u(smc);
    float* biasS = (float*)smc;
    int tid = threadIdx.x, wid = tid >> 5, lane = tid & 31;
    int m0 = blockIdx.y * 128, c0b = blockIdx.x * 64;
    int warp_m = (wid & 3) * 32, warp_n = (wid >> 2) * 32;

    for (int i = tid; i < 64; i += 256) biasS[i] = bih[c0b + i] + bhh[c0b + i];

    int aRow = lane & 15;
    int aKb  = (lane >> 4) * 16;
    int bN   = (lane & 7) + ((lane >> 4) << 3);
    int bKb  = ((lane >> 3) & 1) * 16;

    float acc[2][4][4];
    #pragma unroll
    for (int i = 0; i < 2; i++)
        #pragma unroll
        for (int j = 0; j < 4; j++)
            #pragma unroll
            for (int q = 0; q < 4; q++) acc[i][j][q] = 0.f;

    int arow = tid >> 1, asegb = (tid & 1) * 4;   // A: 128 rows x 8 segs, 4/thread
    int brow = tid >> 2, bsegb = (tid & 3) * 2;   // B: 64 rows x 8 segs, 2/thread

    auto load_chunk = [&](int ch, int buf) {
        int k0 = ch * 64;
        const __nv_bfloat16* fH = g_featH + (size_t)(m0 + arow) * 1024 + k0 + asegb * 8;
        const __nv_bfloat16* fL = g_featL + (size_t)(m0 + arow) * 1024 + k0 + asegb * 8;
        uint32_t daH = sb + G2_AH(buf) + arow * RS2 + asegb * 16;
        uint32_t daL = sb + G2_AL(buf) + arow * RS2 + asegb * 16;
        #pragma unroll
        for (int s = 0; s < 4; s++) {
            CPA16(daH + s * 16, fH + s * 8);
            CPA16(daL + s * 16, fL + s * 8);
        }
        const __nv_bfloat16* wH = g_wihH + (size_t)(c0b + brow) * 1024 + k0 + bsegb * 8;
        const __nv_bfloat16* wL = g_wihL + (size_t)(c0b + brow) * 1024 + k0 + bsegb * 8;
        uint32_t dbH = sb + G2_BH(buf) + brow * RS2 + bsegb * 16;
        uint32_t dbL = sb + G2_BL(buf) + brow * RS2 + bsegb * 16;
        #pragma unroll
        for (int s = 0; s < 2; s++) {
            CPA16(dbH + s * 16, wH + s * 8);
            CPA16(dbL + s * 16, wL + s * 8);
        }
    };

    load_chunk(0, 0);
    asm volatile("cp.async.commit_group;");

    const int NC = 16;
    for (int ch = 0; ch < NC; ch++) {
        int buf = ch & 1;
        if (ch + 1 < NC) {
            load_chunk(ch + 1, buf ^ 1);
            asm volatile("cp.async.commit_group;");
            asm volatile("cp.async.wait_group 1;");
        } else {
            asm volatile("cp.async.wait_group 0;");
        }
        __syncthreads();

        uint32_t aBh = sb + G2_AH(buf) + (warp_m + aRow) * RS2 + aKb;
        uint32_t aBl = sb + G2_AL(buf) + (warp_m + aRow) * RS2 + aKb;
        uint32_t bBh = sb + G2_BH(buf) + (warp_n + bN) * RS2 + bKb;
        uint32_t bBl = sb + G2_BL(buf) + (warp_n + bN) * RS2 + bKb;

        #pragma unroll
        for (int ks = 0; ks < 4; ks++) {
            uint32_t ah[2][4], al[2][4], bh[2][4], bl[2][4];
            #pragma unroll
            for (int mt = 0; mt < 2; mt++) {
                ldsm4(ah[mt], aBh + mt * 16 * RS2 + ks * 32);
                ldsm4(al[mt], aBl + mt * 16 * RS2 + ks * 32);
            }
            #pragma unroll
            for (int nt = 0; nt < 2; nt++) {
                ldsm4(bh[nt], bBh + nt * 16 * RS2 + ks * 32);
                ldsm4(bl[nt], bBl + nt * 16 * RS2 + ks * 32);
            }
            // product loop OUTERMOST: 8 independent accumulators between reuses
            #pragma unroll
            for (int pr = 0; pr < 3; pr++) {
                #pragma unroll
                for (int mt = 0; mt < 2; mt++)
                    #pragma unroll
                    for (int nt = 0; nt < 2; nt++)
                        #pragma unroll
                        for (int f = 0; f < 2; f++) {
                            const uint32_t* av = (pr == 2) ? al[mt] : ah[mt];
                            const uint32_t* bv = (pr == 1) ? &bl[nt][f * 2]
                                                           : &bh[nt][f * 2];
                            mma16816(acc[mt][nt * 2 + f], av, bv);
                        }
            }
        }
        __syncthreads();
    }

    int r0 = lane >> 2, cpair = (lane & 3) * 2;
    #pragma unroll
    for (int mt = 0; mt < 2; mt++) {
        #pragma unroll
        for (int nI = 0; nI < 4; nI++) {
            int colL = warp_n + nI * 8 + cpair;
            int col = c0b + colL;
            float b0 = biasS[colL], b1 = biasS[colL + 1];
            int m = m0 + warp_m + mt * 16 + r0;
            float2 v0 = make_float2(acc[mt][nI][0] + b0, acc[mt][nI][1] + b1);
            float2 v1 = make_float2(acc[mt][nI][2] + b0, acc[mt][nI][3] + b1);
            *(float2*)&g_gatex[(size_t)m * 512 + col] = v0;
            *(float2*)&g_gatex[(size_t)(m + 8) * 512 + col] = v1;
        }
    }
}

// ============================================================
// Kernel 3: persistent LSTM scan, 512 threads, split-K halves.
// ============================================================
#define KSW 108
#define KSPLIT 64
#define SCAN_SMEM_FLOATS (KSW * 512 + 256 + 256 + 1024 + 1024)

__global__ void __launch_bounds__(512, 1)
k_scan(const float* __restrict__ done,
       const float* __restrict__ h0,
       const float* __restrict__ c0,
       float* __restrict__ dout) {
    extern __shared__ float sm[];
    float* Ws = sm;                      // [KSW][512]
    float* hs = sm + KSW * 512;          // [2][128]
    float* cs = hs + 256;                // [2][128]
    float* gs = cs + 256;                // [2][512]
    float4* ps = (float4*)(gs + 1024);   // [256] partials

    int tid = threadIdx.x;
    int tid2 = tid & 255;
    int half = tid >> 8;
    int e0 = blockIdx.x * 2;

    for (int i = tid; i < KSW * 512; i += 512) Ws[i] = g_whhT[i];
    if (tid < 256) {
        int e = tid >> 7, m = tid & 127;
        int env = e0 + e;
        float s = 1.f - done[env];
        hs[tid] = h0[env * HID + m] * s;
        cs[tid] = c0[env * HID + m] * s;
    }
    __syncthreads();

    int j0 = tid2 * 2;
    int gtype = tid2 >> 6;

    for (int t = 0; t < T_STEPS; t++) {
        if (half == 0) {
            const float* gxa = g_gatex + (size_t)(t * B_ENV + e0) * NG;
            const float* gxb = gxa + NG;
            float2 a0 = *(const float2*)&gxa[j0];
            float2 b0 = *(const float2*)&gxb[j0];
            float acc00 = a0.x, acc01 = a0.y;
            float acc10 = b0.x, acc11 = b0.y;
            const float* wp = Ws + j0;
            #pragma unroll 8
            for (int k = 0; k < KSPLIT; k++) {
                float2 w = *(const float2*)wp;
                float ha = hs[k];
                float hb = hs[128 + k];
                acc00 += w.x * ha; acc01 += w.y * ha;
                acc10 += w.x * hb; acc11 += w.y * hb;
                wp += 512;
            }
            __syncthreads();
            float4 p = ps[tid2];
            acc00 += p.x; acc01 += p.y; acc10 += p.z; acc11 += p.w;
            if (gtype == 2) {
                acc00 = tanhf(acc00); acc01 = tanhf(acc01);
                acc10 = tanhf(acc10); acc11 = tanhf(acc11);
            } else {
                acc00 = 1.f / (1.f + __expf(-acc00));
                acc01 = 1.f / (1.f + __expf(-acc01));
                acc10 = 1.f / (1.f + __expf(-acc10));
                acc11 = 1.f / (1.f + __expf(-acc11));
            }
            gs[j0] = acc00;       gs[j0 + 1] = acc01;
            gs[512 + j0] = acc10; gs[512 + j0 + 1] = acc11;
        } else {
            float acc00 = 0.f, acc01 = 0.f, acc10 = 0.f, acc11 = 0.f;
            const float* wp = Ws + KSPLIT * 512 + j0;
            #pragma unroll 8
            for (int k = KSPLIT; k < KSW; k++) {
                float2 w = *(const float2*)wp;
                float ha = hs[k];
                float hb = hs[128 + k];
                acc00 += w.x * ha; acc01 += w.y * ha;
                acc10 += w.x * hb; acc11 += w.y * hb;
                wp += 512;
            }
            const float* wg = g_whhT + KSW * 512 + j0;
            #pragma unroll
            for (int k = KSW; k < HID; k++) {
                float2 w = __ldg((const float2*)wg);
                float ha = hs[k];
                float hb = hs[128 + k];
                acc00 += w.x * ha; acc01 += w.y * ha;
                acc10 += w.x * hb; acc11 += w.y * hb;
                wg += 512;
            }
            ps[tid2] = make_float4(acc00, acc01, acc10, acc11);
            __syncthreads();
        }
        __syncthreads();
        if (tid < 256) {
            int e = tid >> 7, m = tid & 127, env = e0 + e;
            const float* G = gs + e * 512;
            float c = G[128 + m] * cs[tid] + G[m] * G[256 + m];
            float h = G[384 + m] * tanhf(c);
            g_hid[(size_t)(t * B_ENV + env) * HID + m] = h;
            if (t < T_STEPS - 1) {
                float s = 1.f - done[(t + 1) * B_ENV + env];
                hs[tid] = h * s;
                cs[tid] = c * s;
            } else {
                hs[tid] = h;
                cs[tid] = c;
            }
        }
        __syncthreads();
    }

    if (tid < 256) {
        int e = tid >> 7, m = tid & 127, env = e0 + e;
        dout[262144 + env * HID + m]         = hs[tid];
        dout[262144 + 32768 + env * HID + m] = cs[tid];
    }
}

// ============================================================
// Kernel 4: heads
// ============================================================
__global__ void k_head(const float* __restrict__ aw, const float* __restrict__ ab,
                       const float* __restrict__ cw, const float* __restrict__ cb,
                       float* __restrict__ dout) {
    __shared__ float Hs[32 * 128];
    __shared__ float Wsm[8 * 128];
    __shared__ float Bsm[8];
    int tid = threadIdx.x;
    for (int i = tid; i < 896; i += 256) Wsm[i] = aw[i];
    for (int i = tid; i < 128; i += 256) Wsm[896 + i] = cw[i];
    if (tid < 7) Bsm[tid] = ab[tid];
    if (tid == 7) Bsm[7] = cb[0];
    int n0 = blockIdx.x * 32;
    for (int i = tid; i < 4096; i += 256) Hs[i] = g_hid[(size_t)n0 * 128 + i];
    __syncthreads();
    int r = tid >> 3, o = tid & 7;
    const float* h = Hs + r * 128;
    const float* w = Wsm + o * 128;
    float a = Bsm[o];
    #pragma unroll
    for (int k = 0; k < 128; k++) a += h[k] * w[k];
    dout[(size_t)(n0 + r) * 8 + o] = a;
}

// ============================================================
extern "C" void kernel_launch(void* const* d_in, const int* in_sizes, int n_in,
                              void* d_out, int out_size) {
    const float* obs  = (const float*)d_in[0];
    const float* done = (const float*)d_in[1];
    const float* h0   = (const float*)d_in[2];
    const float* c0   = (const float*)d_in[3];
    const float* w1   = (const float*)d_in[4];
    const float* b1   = (const float*)d_in[5];
    const float* w2   = (const float*)d_in[6];
    const float* b2   = (const float*)d_in[7];
    const float* w3   = (const float*)d_in[8];
    const float* b3   = (const float*)d_in[9];
    const float* wih  = (const float*)d_in[10];
    const float* whh  = (const float*)d_in[11];
    const float* bih  = (const float*)d_in[12];
    const float* bhh  = (const float*)d_in[13];
    const float* aw   = (const float*)d_in[14];
    const float* ab   = (const float*)d_in[15];
    const float* cw   = (const float*)d_in[16];
    const float* cb   = (const float*)d_in[17];
    float* out = (float*)d_out;

    cudaFuncSetAttribute(k_conv, cudaFuncAttributeMaxDynamicSharedMemorySize,
                         (CONV_WSM + 8 * CONV_PW) * 4);
    cudaFuncSetAttribute(k_scan, cudaFuncAttributeMaxDynamicSharedMemorySize,
                         SCAN_SMEM_FLOATS * 4);
    cudaFuncSetAttribute(k_gemm_mma, cudaFuncAttributeMaxDynamicSharedMemorySize,
                         G2_TOT);

    k_transpose_whh<<<256, 256>>>(whh);
    k_split_wih<<<2048, 256>>>(wih);
    k_conv<<<4096, 256, (CONV_WSM + 8 * CONV_PW) * 4>>>(obs, w1, b1, w2, b2, w3, b3);
    dim3 gg(8, 256);
    k_gemm_mma<<<gg, 256, G2_TOT>>>(bih, bhh);
    k_scan<<<128, 512, SCAN_SMEM_FLOATS * 4>>>(done, h0, c0, out);
    k_head<<<1024, 256>>>(aw, ab, cw, cb, out);
}

// round 10
// speedup vs baseline: 1.0888x; 1.0888x over previous
#include <cuda_runtime.h>
#include <cuda_bf16.h>
#include <math.h>
#include <stdint.h>

#define T_STEPS 128
#define B_ENV   256
#define N_TOT   (T_STEPS * B_ENV)   // 32768
#define HID     128
#define NFLAT   1024
#define NG      512                  // 4*HID

// -------- scratch (static device arrays; no allocation) --------
__device__ float g_gatex[N_TOT * NG];            // 64 MB
__device__ float g_whhT [HID * NG];              // 256 KB
__device__ float g_hid  [N_TOT * HID];           // 16 MB
__device__ __nv_bfloat16 g_featH[N_TOT * NFLAT]; // 64 MB
__device__ __nv_bfloat16 g_featL[N_TOT * NFLAT]; // 64 MB
__device__ __nv_bfloat16 g_wihH [NG * NFLAT];    // 1 MB
__device__ __nv_bfloat16 g_wihL [NG * NFLAT];    // 1 MB

// ================= helpers =================
__device__ __forceinline__ uint32_t s2u(const void* p) {
    uint32_t a;
    asm("{ .reg .u64 t; cvta.to.shared.u64 t, %1; cvt.u32.u64 %0, t; }"
        : "=r"(a) : "l"(p));
    return a;
}
__device__ __forceinline__ void ldsm4(uint32_t* r, uint32_t addr) {
    asm volatile("ldmatrix.sync.aligned.m8n8.x4.shared.b16 {%0,%1,%2,%3}, [%4];"
                 : "=r"(r[0]), "=r"(r[1]), "=r"(r[2]), "=r"(r[3]) : "r"(addr));
}
__device__ __forceinline__ void mma16816(float* d, const uint32_t* a, const uint32_t* b) {
    asm volatile(
        "mma.sync.aligned.m16n8k16.row.col.f32.bf16.bf16.f32 "
        "{%0,%1,%2,%3}, {%4,%5,%6,%7}, {%8,%9}, {%0,%1,%2,%3};"
        : "+f"(d[0]), "+f"(d[1]), "+f"(d[2]), "+f"(d[3])
        : "r"(a[0]), "r"(a[1]), "r"(a[2]), "r"(a[3]), "r"(b[0]), "r"(b[1]));
}
#define CPA16(dst, src) \
    asm volatile("cp.async.cg.shared.global [%0], [%1], 16;" :: "r"(dst), "l"(src))

// ============================================================
// Kernel 0a: transpose w_hh [512,128] -> w_hhT [128,512]
// ============================================================
__global__ void k_transpose_whh(const float* __restrict__ whh) {
    int idx = blockIdx.x * blockDim.x + threadIdx.x;
    if (idx < NG * HID) {
        int k = idx >> 9;
        int j = idx & 511;
        g_whhT[idx] = whh[j * HID + k];
    }
}

// ============================================================
// Kernel 0b: split w_ih into bf16 hi/lo
// ============================================================
__global__ void k_split_wih(const float* __restrict__ wih) {
    int idx = blockIdx.x * blockDim.x + threadIdx.x;
    if (idx < NG * NFLAT) {
        float v = wih[idx];
        __nv_bfloat16 h = __float2bfloat16(v);
        g_wihH[idx] = h;
        g_wihL[idx] = __float2bfloat16(v - __bfloat162float(h));
    }
}

// ============================================================
// Kernel 1: fused conv stack, register-blocked by output channel.
// (R6 proven version: writes bf16 hi AND lo feat.)
// ============================================================
#define CONV_WSM 10544
#define CONV_PW  1523

__global__ void __launch_bounds__(256)
k_conv(const float* __restrict__ obs,
       const float* __restrict__ w1, const float* __restrict__ b1,
       const float* __restrict__ w2, const float* __restrict__ b2,
       const float* __restrict__ w3, const float* __restrict__ b3) {
    extern __shared__ float sm[];
    float* W1 = sm;
    float* B1 = sm + 192;
    float* W2 = sm + 208;
    float* B2 = sm + 2256;
    float* W3 = sm + 2288;
    float* B3 = sm + 10480;
    int tid = threadIdx.x;
    for (int i = tid; i < 192;  i += 256) W1[i] = w1[i];
    for (int i = tid; i < 16;   i += 256) B1[i] = b1[i];
    for (int i = tid; i < 2048; i += 256) W2[i] = w2[i];
    for (int i = tid; i < 32;   i += 256) B2[i] = b2[i];
    for (int i = tid; i < 8192; i += 256) W3[i] = w3[i];
    for (int i = tid; i < 64;   i += 256) B3[i] = b3[i];
    __syncthreads();

    int warp = tid >> 5, lane = tid & 31;
    int n = blockIdx.x * 8 + warp;
    float* buf = sm + CONV_WSM + warp * CONV_PW;
    float* O  = buf;          // obs [7][7][3] HWC
    float* X1 = buf + 147;    // [16][6][6]
    float* X2 = buf + 723;    // [32][5][5]

    const float* op = obs + (size_t)n * 147;
    for (int i = lane; i < 147; i += 32) O[i] = op[i];
    __syncwarp();

    // ---- conv1: lane = (ch, row-half) ----
    {
        int ch = lane >> 1, half = lane & 1, y0 = half * 3;
        float acc[3][6];
        float bv = B1[ch];
        #pragma unroll
        for (int r = 0; r < 3; r++)
            #pragma unroll
            for (int x = 0; x < 6; x++) acc[r][x] = bv;
        for (int ci = 0; ci < 3; ci++) {
            const float* w = W1 + ch * 12 + ci * 4;
            float w0 = w[0], w1v = w[1], w2v = w[2], w3v = w[3];
            float in[4][7];
            #pragma unroll
            for (int r = 0; r < 4; r++)
                #pragma unroll
                for (int x = 0; x < 7; x++)
                    in[r][x] = O[((y0 + r) * 7 + x) * 3 + ci];
            #pragma unroll
            for (int r = 0; r < 3; r++)
                #pragma unroll
                for (int x = 0; x < 6; x++)
                    acc[r][x] += in[r][x] * w0 + in[r][x + 1] * w1v
                               + in[r + 1][x] * w2v + in[r + 1][x + 1] * w3v;
        }
        #pragma unroll
        for (int r = 0; r < 3; r++)
            #pragma unroll
            for (int x = 0; x < 6; x++)
                X1[ch * 36 + (y0 + r) * 6 + x] = fmaxf(acc[r][x], 0.f);
    }
    __syncwarp();

    // ---- conv2: lane = ch in [0,32) ----
    {
        int ch = lane;
        float acc[5][5];
        float bv = B2[ch];
        #pragma unroll
        for (int y = 0; y < 5; y++)
            #pragma unroll
            for (int x = 0; x < 5; x++) acc[y][x] = bv;
        for (int ci = 0; ci < 16; ci++) {
            const float* w = W2 + ch * 64 + ci * 4;
            float w0 = w[0], w1v = w[1], w2v = w[2], w3v = w[3];
            float in[6][6];
            const float* xp = X1 + ci * 36;
            #pragma unroll
            for (int y = 0; y < 6; y++)
                #pragma unroll
                for (int x = 0; x < 6; x++) in[y][x] = xp[y * 6 + x];
            #pragma unroll
            for (int y = 0; y < 5; y++)
                #pragma unroll
                for (int x = 0; x < 5; x++)
                    acc[y][x] += in[y][x] * w0 + in[y][x + 1] * w1v
                               + in[y + 1][x] * w2v + in[y + 1][x + 1] * w3v;
        }
        #pragma unroll
        for (int y = 0; y < 5; y++)
            #pragma unroll
            for (int x = 0; x < 5; x++)
                X2[ch * 25 + y * 5 + x] = fmaxf(acc[y][x], 0.f);
    }
    __syncwarp();

    // ---- conv3: lane owns channels (lane, lane+32) ----
    {
        int ca = lane, cb = lane + 32;
        float a0[4][4], a1[4][4];
        float bva = B3[ca], bvb = B3[cb];
        #pragma unroll
        for (int y = 0; y < 4; y++)
            #pragma unroll
            for (int x = 0; x < 4; x++) { a0[y][x] = bva; a1[y][x] = bvb; }
        for (int ci = 0; ci < 32; ci++) {
            const float* wa = W3 + ca * 128 + ci * 4;
            const float* wb = W3 + cb * 128 + ci * 4;
            float wa0 = wa[0], wa1 = wa[1], wa2 = wa[2], wa3 = wa[3];
            float wb0 = wb[0], wb1 = wb[1], wb2 = wb[2], wb3 = wb[3];
            float in[5][5];
            const float* xp = X2 + ci * 25;
            #pragma unroll
            for (int y = 0; y < 5; y++)
                #pragma unroll
                for (int x = 0; x < 5; x++) in[y][x] = xp[y * 5 + x];
            #pragma unroll
            for (int y = 0; y < 4; y++)
                #pragma unroll
                for (int x = 0; x < 4; x++) {
                    a0[y][x] += in[y][x] * wa0 + in[y][x + 1] * wa1
                              + in[y + 1][x] * wa2 + in[y + 1][x + 1] * wa3;
                    a1[y][x] += in[y][x] * wb0 + in[y][x + 1] * wb1
                              + in[y + 1][x] * wb2 + in[y + 1][x + 1] * wb3;
                }
        }
        __nv_bfloat162* ohA = (__nv_bfloat162*)(g_featH + (size_t)n * NFLAT + ca * 16);
        __nv_bfloat162* olA = (__nv_bfloat162*)(g_featL + (size_t)n * NFLAT + ca * 16);
        __nv_bfloat162* ohB = (__nv_bfloat162*)(g_featH + (size_t)n * NFLAT + cb * 16);
        __nv_bfloat162* olB = (__nv_bfloat162*)(g_featL + (size_t)n * NFLAT + cb * 16);
        #pragma unroll
        for (int q = 0; q < 8; q++) {
            int y = q >> 1, x = (q & 1) * 2;
            float v0 = fmaxf(a0[y][x], 0.f), v1 = fmaxf(a0[y][x + 1], 0.f);
            __nv_bfloat16 h0v = __float2bfloat16(v0), h1v = __float2bfloat16(v1);
            ohA[q] = __nv_bfloat162(h0v, h1v);
            olA[q] = __nv_bfloat162(
                __float2bfloat16(v0 - __bfloat162float(h0v)),
                __float2bfloat16(v1 - __bfloat162float(h1v)));
            float u0 = fmaxf(a1[y][x], 0.f), u1 = fmaxf(a1[y][x + 1], 0.f);
            __nv_bfloat16 g0v = __float2bfloat16(u0), g1v = __float2bfloat16(u1);
            ohB[q] = __nv_bfloat162(g0v, g1v);
            olB[q] = __nv_bfloat162(
                __float2bfloat16(u0 - __bfloat162float(g0v)),
                __float2bfloat16(u1 - __bfloat162float(g1v)));
        }
    }
}

// ============================================================
// Kernel 2: 3-product split-bf16 GEMM via mma.sync, BK=32,
// 3-stage cp.async pipeline. D = Ah@Bh + Ah@Bl + Al@Bh + bias.
// grid = (8 colblk, 256 rowblk) for L2 reuse of A.
// ============================================================
#define RS 80                        // padded row stride bytes
#define G_STAGE 30720                // AH 10240 + AL 10240 + BH 5120 + BL 5120
#define G_AH(s) (256 + (s) * G_STAGE)
#define G_AL(s) (G_AH(s) + 10240)
#define G_BH(s) (G_AH(s) + 20480)
#define G_BL(s) (G_AH(s) + 25600)
#define G_TOT (256 + 3 * G_STAGE)    // 92416 bytes

__global__ void __launch_bounds__(256, 2)
k_gemm_mma(const float* __restrict__ bih, const float* __restrict__ bhh) {
    extern __shared__ char smc[];
    uint32_t sb = s2u(smc);
    float* biasS = (float*)smc;
    int tid = threadIdx.x, wid = tid >> 5, lane = tid & 31;
    int m0 = blockIdx.y * 128, c0b = blockIdx.x * 64;
    int warp_m = (wid & 3) * 32, warp_n = (wid >> 2) * 32;

    for (int i = tid; i < 64; i += 256) biasS[i] = bih[c0b + i] + bhh[c0b + i];

    int aRow = lane & 15;
    int aKb  = (lane >> 4) * 16;
    int bN   = (lane & 7) + ((lane >> 4) << 3);
    int bKb  = ((lane >> 3) & 1) * 16;

    float acc[2][4][4];
    #pragma unroll
    for (int i = 0; i < 2; i++)
        #pragma unroll
        for (int j = 0; j < 4; j++)
            #pragma unroll
            for (int q = 0; q < 4; q++) acc[i][j][q] = 0.f;

    int arow = tid >> 1, aseg2 = (tid & 1) * 2;   // A: 128 rows x 4 segs, 2/thr (x2 hi/lo)
    int brow = tid >> 2, bseg = tid & 3;          // B: 64 rows x 4 segs, 1/thr (x2 hi/lo)

    auto load_chunk = [&](int ch, int s) {
        int k0 = ch * 32;
        const __nv_bfloat16* fH = g_featH + (size_t)(m0 + arow) * 1024 + k0 + aseg2 * 8;
        const __nv_bfloat16* fL = g_featL + (size_t)(m0 + arow) * 1024 + k0 + aseg2 * 8;
        uint32_t daH = sb + G_AH(s) + arow * RS + aseg2 * 16;
        uint32_t daL = sb + G_AL(s) + arow * RS + aseg2 * 16;
        CPA16(daH, fH);      CPA16(daH + 16, fH + 8);
        CPA16(daL, fL);      CPA16(daL + 16, fL + 8);
        const __nv_bfloat16* wH = g_wihH + (size_t)(c0b + brow) * 1024 + k0 + bseg * 8;
        const __nv_bfloat16* wL = g_wihL + (size_t)(c0b + brow) * 1024 + k0 + bseg * 8;
        CPA16(sb + G_BH(s) + brow * RS + bseg * 16, wH);
        CPA16(sb + G_BL(s) + brow * RS + bseg * 16, wL);
    };

    const int NC = 32;
    load_chunk(0, 0);
    asm volatile("cp.async.commit_group;");
    load_chunk(1, 1);
    asm volatile("cp.async.commit_group;");

    for (int ch = 0; ch < NC; ch++) {
        int s = ch % 3;
        if (ch < NC - 1)
            asm volatile("cp.async.wait_group 1;");
        else
            asm volatile("cp.async.wait_group 0;");
        __syncthreads();

        if (ch + 2 < NC) {
            load_chunk(ch + 2, (ch + 2) % 3);
            asm volatile("cp.async.commit_group;");
        }

        uint32_t aBh = sb + G_AH(s) + (warp_m + aRow) * RS + aKb;
        uint32_t aBl = sb + G_AL(s) + (warp_m + aRow) * RS + aKb;
        uint32_t bBh = sb + G_BH(s) + (warp_n + bN) * RS + bKb;
        uint32_t bBl = sb + G_BL(s) + (warp_n + bN) * RS + bKb;

        #pragma unroll
        for (int ks = 0; ks < 2; ks++) {
            uint32_t ah[2][4], al[2][4], bh[2][4], bl[2][4];
            #pragma unroll
            for (int mt = 0; mt < 2; mt++) {
                ldsm4(ah[mt], aBh + mt * 16 * RS + ks * 32);
                ldsm4(al[mt], aBl + mt * 16 * RS + ks * 32);
            }
            #pragma unroll
            for (int nt = 0; nt < 2; nt++) {
                ldsm4(bh[nt], bBh + nt * 16 * RS + ks * 32);
                ldsm4(bl[nt], bBl + nt * 16 * RS + ks * 32);
            }
            // R6-proven inner ordering
            #pragma unroll
            for (int mt = 0; mt < 2; mt++)
                #pragma unroll
                for (int nt = 0; nt < 2; nt++)
                    #pragma unroll
                    for (int f = 0; f < 2; f++) {
                        float* d = acc[mt][nt * 2 + f];
                        mma16816(d, ah[mt], &bh[nt][f * 2]);
                        mma16816(d, ah[mt], &bl[nt][f * 2]);
                        mma16816(d, al[mt], &bh[nt][f * 2]);
                    }
        }
        __syncthreads();
    }

    int r0 = lane >> 2, cpair = (lane & 3) * 2;
    #pragma unroll
    for (int mt = 0; mt < 2; mt++) {
        #pragma unroll
        for (int nI = 0; nI < 4; nI++) {
            int colL = warp_n + nI * 8 + cpair;
            int col = c0b + colL;
            float b0 = biasS[colL], b1 = biasS[colL + 1];
            int m = m0 + warp_m + mt * 16 + r0;
            float2 v0 = make_float2(acc[mt][nI][0] + b0, acc[mt][nI][1] + b1);
            float2 v1 = make_float2(acc[mt][nI][2] + b0, acc[mt][nI][3] + b1);
            *(float2*)&g_gatex[(size_t)m * 512 + col] = v0;
            *(float2*)&g_gatex[(size_t)(m + 8) * 512 + col] = v1;
        }
    }
}

// ============================================================
// Kernel 3: persistent LSTM scan, 512 threads, split-K halves.
// ============================================================
#define KSW 108
#define KSPLIT 64
#define SCAN_SMEM_FLOATS (KSW * 512 + 256 + 256 + 1024 + 1024)

__global__ void __launch_bounds__(512, 1)
k_scan(const float* __restrict__ done,
       const float* __restrict__ h0,
       const float* __restrict__ c0,
       float* __restrict__ dout) {
    extern __shared__ float sm[];
    float* Ws = sm;                      // [KSW][512]
    float* hs = sm + KSW * 512;          // [2][128]
    float* cs = hs + 256;                // [2][128]
    float* gs = cs + 256;                // [2][512]
    float4* ps = (float4*)(gs + 1024);   // [256] partials

    int tid = threadIdx.x;
    int tid2 = tid & 255;
    int half = tid >> 8;
    int e0 = blockIdx.x * 2;

    for (int i = tid; i < KSW * 512; i += 512) Ws[i] = g_whhT[i];
    if (tid < 256) {
        int e = tid >> 7, m = tid & 127;
        int env = e0 + e;
        float s = 1.f - done[env];
        hs[tid] = h0[env * HID + m] * s;
        cs[tid] = c0[env * HID + m] * s;
    }
    __syncthreads();

    int j0 = tid2 * 2;
    int gtype = tid2 >> 6;

    for (int t = 0; t < T_STEPS; t++) {
        if (half == 0) {
            const float* gxa = g_gatex + (size_t)(t * B_ENV + e0) * NG;
            const float* gxb = gxa + NG;
            float2 a0 = *(const float2*)&gxa[j0];
            float2 b0 = *(const float2*)&gxb[j0];
            float acc00 = a0.x, acc01 = a0.y;
            float acc10 = b0.x, acc11 = b0.y;
            const float* wp = Ws + j0;
            #pragma unroll 8
            for (int k = 0; k < KSPLIT; k++) {
                float2 w = *(const float2*)wp;
                float ha = hs[k];
                float hb = hs[128 + k];
                acc00 += w.x * ha; acc01 += w.y * ha;
                acc10 += w.x * hb; acc11 += w.y * hb;
                wp += 512;
            }
            __syncthreads();
            float4 p = ps[tid2];
            acc00 += p.x; acc01 += p.y; acc10 += p.z; acc11 += p.w;
            if (gtype == 2) {
                acc00 = tanhf(acc00); acc01 = tanhf(acc01);
                acc10 = tanhf(acc10); acc11 = tanhf(acc11);
            } else {
                acc00 = 1.f / (1.f + __expf(-acc00));
                acc01 = 1.f / (1.f + __expf(-acc01));
                acc10 = 1.f / (1.f + __expf(-acc10));
                acc11 = 1.f / (1.f + __expf(-acc11));
            }
            gs[j0] = acc00;       gs[j0 + 1] = acc01;
            gs[512 + j0] = acc10; gs[512 + j0 + 1] = acc11;
        } else {
            float acc00 = 0.f, acc01 = 0.f, acc10 = 0.f, acc11 = 0.f;
            const float* wp = Ws + KSPLIT * 512 + j0;
            #pragma unroll 8
            for (int k = KSPLIT; k < KSW; k++) {
                float2 w = *(const float2*)wp;
                float ha = hs[k];
                float hb = hs[128 + k];
                acc00 += w.x * ha; acc01 += w.y * ha;
                acc10 += w.x * hb; acc11 += w.y * hb;
                wp += 512;
            }
            const float* wg = g_whhT + KSW * 512 + j0;
            #pragma unroll
            for (int k = KSW; k < HID; k++) {
                float2 w = __ldg((const float2*)wg);
                float ha = hs[k];
                float hb = hs[128 + k];
                acc00 += w.x * ha; acc01 += w.y * ha;
                acc10 += w.x * hb; acc11 += w.y * hb;
                wg += 512;
            }
            ps[tid2] = make_float4(acc00, acc01, acc10, acc11);
            __syncthreads();
        }
        __syncthreads();
        if (tid < 256) {
            int e = tid >> 7, m = tid & 127, env = e0 + e;
            const float* G = gs + e * 512;
            float c = G[128 + m] * cs[tid] + G[m] * G[256 + m];
            float h = G[384 + m] * tanhf(c);
            g_hid[(size_t)(t * B_ENV + env) * HID + m] = h;
            if (t < T_STEPS - 1) {
                float s = 1.f - done[(t + 1) * B_ENV + env];
                hs[tid] = h * s;
                cs[tid] = c * s;
            } else {
                hs[tid] = h;
                cs[tid] = c;
            }
        }
        __syncthreads();
    }

    if (tid < 256) {
        int e = tid >> 7, m = tid & 127, env = e0 + e;
        dout[262144 + env * HID + m]         = hs[tid];
        dout[262144 + 32768 + env * HID + m] = cs[tid];
    }
}

// ============================================================
// Kernel 4: heads
// ============================================================
__global__ void k_head(const float* __restrict__ aw, const float* __restrict__ ab,
                       const float* __restrict__ cw, const float* __restrict__ cb,
                       float* __restrict__ dout) {
    __shared__ float Hs[32 * 128];
    __shared__ float Wsm[8 * 128];
    __shared__ float Bsm[8];
    int tid = threadIdx.x;
    for (int i = tid; i < 896; i += 256) Wsm[i] = aw[i];
    for (int i = tid; i < 128; i += 256) Wsm[896 + i] = cw[i];
    if (tid < 7) Bsm[tid] = ab[tid];
    if (tid == 7) Bsm[7] = cb[0];
    int n0 = blockIdx.x * 32;
    for (int i = tid; i < 4096; i += 256) Hs[i] = g_hid[(size_t)n0 * 128 + i];
    __syncthreads();
    int r = tid >> 3, o = tid & 7;
    const float* h = Hs + r * 128;
    const float* w = Wsm + o * 128;
    float a = Bsm[o];
    #pragma unroll
    for (int k = 0; k < 128; k++) a += h[k] * w[k];
    dout[(size_t)(n0 + r) * 8 + o] = a;
}

// ============================================================
extern "C" void kernel_launch(void* const* d_in, const int* in_sizes, int n_in,
                              void* d_out, int out_size) {
    const float* obs  = (const float*)d_in[0];
    const float* done = (const float*)d_in[1];
    const float* h0   = (const float*)d_in[2];
    const float* c0   = (const float*)d_in[3];
    const float* w1   = (const float*)d_in[4];
    const float* b1   = (const float*)d_in[5];
    const float* w2   = (const float*)d_in[6];
    const float* b2   = (const float*)d_in[7];
    const float* w3   = (const float*)d_in[8];
    const float* b3   = (const float*)d_in[9];
    const float* wih  = (const float*)d_in[10];
    const float* whh  = (const float*)d_in[11];
    const float* bih  = (const float*)d_in[12];
    const float* bhh  = (const float*)d_in[13];
    const float* aw   = (const float*)d_in[14];
    const float* ab   = (const float*)d_in[15];
    const float* cw   = (const float*)d_in[16];
    const float* cb   = (const float*)d_in[17];
    float* out = (float*)d_out;

    cudaFuncSetAttribute(k_conv, cudaFuncAttributeMaxDynamicSharedMemorySize,
                         (CONV_WSM + 8 * CONV_PW) * 4);
    cudaFuncSetAttribute(k_scan, cudaFuncAttributeMaxDynamicSharedMemorySize,
                         SCAN_SMEM_FLOATS * 4);
    cudaFuncSetAttribute(k_gemm_mma, cudaFuncAttributeMaxDynamicSharedMemorySize,
                         G_TOT);

    k_transpose_whh<<<256, 256>>>(whh);
    k_split_wih<<<2048, 256>>>(wih);
    k_conv<<<4096, 256, (CONV_WSM + 8 * CONV_PW) * 4>>>(obs, w1, b1, w2, b2, w3, b3);
    dim3 gg(8, 256);
    k_gemm_mma<<<gg, 256, G_TOT>>>(bih, bhh);
    k_scan<<<128, 512, SCAN_SMEM_FLOATS * 4>>>(done, h0, c0, out);
    k_head<<<1024, 256>>>(aw, ab, cw, cb, out);
}

// round 11
// speedup vs baseline: 1.1195x; 1.0282x over previous
#include <cuda_runtime.h>
#include <cuda_bf16.h>
#include <math.h>
#include <stdint.h>

#define T_STEPS 128
#define B_ENV   256
#define N_TOT   (T_STEPS * B_ENV)   // 32768
#define HID     128
#define NFLAT   1024
#define NG      512                  // 4*HID

// -------- scratch (static device arrays; no allocation) --------
__device__ float g_gatex[N_TOT * NG];            // 64 MB
__device__ float g_whhT [HID * NG];              // 256 KB
__device__ __nv_bfloat16 g_featH[N_TOT * NFLAT]; // 64 MB
__device__ __nv_bfloat16 g_featL[N_TOT * NFLAT]; // 64 MB
__device__ __nv_bfloat16 g_wihH [NG * NFLAT];    // 1 MB
__device__ __nv_bfloat16 g_wihL [NG * NFLAT];    // 1 MB

// ================= helpers =================
__device__ __forceinline__ uint32_t s2u(const void* p) {
    uint32_t a;
    asm("{ .reg .u64 t; cvta.to.shared.u64 t, %1; cvt.u32.u64 %0, t; }"
        : "=r"(a) : "l"(p));
    return a;
}
__device__ __forceinline__ void ldsm4(uint32_t* r, uint32_t addr) {
    asm volatile("ldmatrix.sync.aligned.m8n8.x4.shared.b16 {%0,%1,%2,%3}, [%4];"
                 : "=r"(r[0]), "=r"(r[1]), "=r"(r[2]), "=r"(r[3]) : "r"(addr));
}
__device__ __forceinline__ void mma16816(float* d, const uint32_t* a, const uint32_t* b) {
    asm volatile(
        "mma.sync.aligned.m16n8k16.row.col.f32.bf16.bf16.f32 "
        "{%0,%1,%2,%3}, {%4,%5,%6,%7}, {%8,%9}, {%0,%1,%2,%3};"
        : "+f"(d[0]), "+f"(d[1]), "+f"(d[2]), "+f"(d[3])
        : "r"(a[0]), "r"(a[1]), "r"(a[2]), "r"(a[3]), "r"(b[0]), "r"(b[1]));
}
#define CPA16(dst, src) \
    asm volatile("cp.async.cg.shared.global [%0], [%1], 16;" :: "r"(dst), "l"(src))

// ============================================================
// Kernel 0a: transpose w_hh [512,128] -> w_hhT [128,512]
// ============================================================
__global__ void k_transpose_whh(const float* __restrict__ whh) {
    int idx = blockIdx.x * blockDim.x + threadIdx.x;
    if (idx < NG * HID) {
        int k = idx >> 9;
        int j = idx & 511;
        g_whhT[idx] = whh[j * HID + k];
    }
}

// ============================================================
// Kernel 0b: split w_ih into bf16 hi/lo
// ============================================================
__global__ void k_split_wih(const float* __restrict__ wih) {
    int idx = blockIdx.x * blockDim.x + threadIdx.x;
    if (idx < NG * NFLAT) {
        float v = wih[idx];
        __nv_bfloat16 h = __float2bfloat16(v);
        g_wihH[idx] = h;
        g_wihL[idx] = __float2bfloat16(v - __bfloat162float(h));
    }
}

// ============================================================
// Kernel 1: fused conv stack, register-blocked by output channel.
// (R6 proven version: writes bf16 hi AND lo feat.)
// ============================================================
#define CONV_WSM 10544
#define CONV_PW  1523

__global__ void __launch_bounds__(256)
k_conv(const float* __restrict__ obs,
       const float* __restrict__ w1, const float* __restrict__ b1,
       const float* __restrict__ w2, const float* __restrict__ b2,
       const float* __restrict__ w3, const float* __restrict__ b3) {
    extern __shared__ float sm[];
    float* W1 = sm;
    float* B1 = sm + 192;
    float* W2 = sm + 208;
    float* B2 = sm + 2256;
    float* W3 = sm + 2288;
    float* B3 = sm + 10480;
    int tid = threadIdx.x;
    for (int i = tid; i < 192;  i += 256) W1[i] = w1[i];
    for (int i = tid; i < 16;   i += 256) B1[i] = b1[i];
    for (int i = tid; i < 2048; i += 256) W2[i] = w2[i];
    for (int i = tid; i < 32;   i += 256) B2[i] = b2[i];
    for (int i = tid; i < 8192; i += 256) W3[i] = w3[i];
    for (int i = tid; i < 64;   i += 256) B3[i] = b3[i];
    __syncthreads();

    int warp = tid >> 5, lane = tid & 31;
    int n = blockIdx.x * 8 + warp;
    float* buf = sm + CONV_WSM + warp * CONV_PW;
    float* O  = buf;          // obs [7][7][3] HWC
    float* X1 = buf + 147;    // [16][6][6]
    float* X2 = buf + 723;    // [32][5][5]

    const float* op = obs + (size_t)n * 147;
    for (int i = lane; i < 147; i += 32) O[i] = op[i];
    __syncwarp();

    // ---- conv1: lane = (ch, row-half) ----
    {
        int ch = lane >> 1, half = lane & 1, y0 = half * 3;
        float acc[3][6];
        float bv = B1[ch];
        #pragma unroll
        for (int r = 0; r < 3; r++)
            #pragma unroll
            for (int x = 0; x < 6; x++) acc[r][x] = bv;
        for (int ci = 0; ci < 3; ci++) {
            const float* w = W1 + ch * 12 + ci * 4;
            float w0 = w[0], w1v = w[1], w2v = w[2], w3v = w[3];
            float in[4][7];
            #pragma unroll
            for (int r = 0; r < 4; r++)
                #pragma unroll
                for (int x = 0; x < 7; x++)
                    in[r][x] = O[((y0 + r) * 7 + x) * 3 + ci];
            #pragma unroll
            for (int r = 0; r < 3; r++)
                #pragma unroll
                for (int x = 0; x < 6; x++)
                    acc[r][x] += in[r][x] * w0 + in[r][x + 1] * w1v
                               + in[r + 1][x] * w2v + in[r + 1][x + 1] * w3v;
        }
        #pragma unroll
        for (int r = 0; r < 3; r++)
            #pragma unroll
            for (int x = 0; x < 6; x++)
                X1[ch * 36 + (y0 + r) * 6 + x] = fmaxf(acc[r][x], 0.f);
    }
    __syncwarp();

    // ---- conv2: lane = ch in [0,32) ----
    {
        int ch = lane;
        float acc[5][5];
        float bv = B2[ch];
        #pragma unroll
        for (int y = 0; y < 5; y++)
            #pragma unroll
            for (int x = 0; x < 5; x++) acc[y][x] = bv;
        for (int ci = 0; ci < 16; ci++) {
            const float* w = W2 + ch * 64 + ci * 4;
            float w0 = w[0], w1v = w[1], w2v = w[2], w3v = w[3];
            float in[6][6];
            const float* xp = X1 + ci * 36;
            #pragma unroll
            for (int y = 0; y < 6; y++)
                #pragma unroll
                for (int x = 0; x < 6; x++) in[y][x] = xp[y * 6 + x];
            #pragma unroll
            for (int y = 0; y < 5; y++)
                #pragma unroll
                for (int x = 0; x < 5; x++)
                    acc[y][x] += in[y][x] * w0 + in[y][x + 1] * w1v
                               + in[y + 1][x] * w2v + in[y + 1][x + 1] * w3v;
        }
        #pragma unroll
        for (int y = 0; y < 5; y++)
            #pragma unroll
            for (int x = 0; x < 5; x++)
                X2[ch * 25 + y * 5 + x] = fmaxf(acc[y][x], 0.f);
    }
    __syncwarp();

    // ---- conv3: lane owns channels (lane, lane+32) ----
    {
        int ca = lane, cb = lane + 32;
        float a0[4][4], a1[4][4];
        float bva = B3[ca], bvb = B3[cb];
        #pragma unroll
        for (int y = 0; y < 4; y++)
            #pragma unroll
            for (int x = 0; x < 4; x++) { a0[y][x] = bva; a1[y][x] = bvb; }
        for (int ci = 0; ci < 32; ci++) {
            const float* wa = W3 + ca * 128 + ci * 4;
            const float* wb = W3 + cb * 128 + ci * 4;
            float wa0 = wa[0], wa1 = wa[1], wa2 = wa[2], wa3 = wa[3];
            float wb0 = wb[0], wb1 = wb[1], wb2 = wb[2], wb3 = wb[3];
            float in[5][5];
            const float* xp = X2 + ci * 25;
            #pragma unroll
            for (int y = 0; y < 5; y++)
                #pragma unroll
                for (int x = 0; x < 5; x++) in[y][x] = xp[y * 5 + x];
            #pragma unroll
            for (int y = 0; y < 4; y++)
                #pragma unroll
                for (int x = 0; x < 4; x++) {
                    a0[y][x] += in[y][x] * wa0 + in[y][x + 1] * wa1
                              + in[y + 1][x] * wa2 + in[y + 1][x + 1] * wa3;
                    a1[y][x] += in[y][x] * wb0 + in[y][x + 1] * wb1
                              + in[y + 1][x] * wb2 + in[y + 1][x + 1] * wb3;
                }
        }
        __nv_bfloat162* ohA = (__nv_bfloat162*)(g_featH + (size_t)n * NFLAT + ca * 16);
        __nv_bfloat162* olA = (__nv_bfloat162*)(g_featL + (size_t)n * NFLAT + ca * 16);
        __nv_bfloat162* ohB = (__nv_bfloat162*)(g_featH + (size_t)n * NFLAT + cb * 16);
        __nv_bfloat162* olB = (__nv_bfloat162*)(g_featL + (size_t)n * NFLAT + cb * 16);
        #pragma unroll
        for (int q = 0; q < 8; q++) {
            int y = q >> 1, x = (q & 1) * 2;
            float v0 = fmaxf(a0[y][x], 0.f), v1 = fmaxf(a0[y][x + 1], 0.f);
            __nv_bfloat16 h0v = __float2bfloat16(v0), h1v = __float2bfloat16(v1);
            ohA[q] = __nv_bfloat162(h0v, h1v);
            olA[q] = __nv_bfloat162(
                __float2bfloat16(v0 - __bfloat162float(h0v)),
                __float2bfloat16(v1 - __bfloat162float(h1v)));
            float u0 = fmaxf(a1[y][x], 0.f), u1 = fmaxf(a1[y][x + 1], 0.f);
            __nv_bfloat16 g0v = __float2bfloat16(u0), g1v = __float2bfloat16(u1);
            ohB[q] = __nv_bfloat162(g0v, g1v);
            olB[q] = __nv_bfloat162(
                __float2bfloat16(u0 - __bfloat162float(g0v)),
                __float2bfloat16(u1 - __bfloat162float(g1v)));
        }
    }
}

// ============================================================
// Kernel 2: 3-product split-bf16 GEMM via mma.sync.
// BM=128, BN=128, BK=32, warp tile 32x64, sequenced products
// (HH -> LH -> HL) to cap live operand registers.
// grid = (4 colblk, 256 rowblk). 2-stage cp.async pipeline.
// ============================================================
#define RS 80                        // padded row stride bytes
#define GB_STAGE 40960               // AH+AL+BH+BL, 10240 each
#define GB_AH(s) (512 + (s) * GB_STAGE)
#define GB_AL(s) (GB_AH(s) + 10240)
#define GB_BH(s) (GB_AH(s) + 20480)
#define GB_BL(s) (GB_AH(s) + 30720)
#define GB_TOT (512 + 2 * GB_STAGE)  // 82432 bytes

__global__ void __launch_bounds__(256, 2)
k_gemm_mma(const float* __restrict__ bih, const float* __restrict__ bhh) {
    extern __shared__ char smc[];
    uint32_t sb = s2u(smc);
    float* biasS = (float*)smc;      // 128 floats
    int tid = threadIdx.x, wid = tid >> 5, lane = tid & 31;
    int m0 = blockIdx.y * 128, c0b = blockIdx.x * 128;
    int warp_m = (wid & 3) * 32, warp_n = (wid >> 2) * 64;

    for (int i = tid; i < 128; i += 256) biasS[i] = bih[c0b + i] + bhh[c0b + i];

    int aRow = lane & 15;
    int aKb  = (lane >> 4) * 16;
    int bN   = (lane & 7) + ((lane >> 4) << 3);
    int bKb  = ((lane >> 3) & 1) * 16;

    float acc[2][8][4];
    #pragma unroll
    for (int i = 0; i < 2; i++)
        #pragma unroll
        for (int j = 0; j < 8; j++)
            #pragma unroll
            for (int q = 0; q < 4; q++) acc[i][j][q] = 0.f;

    int arow = tid >> 1, aseg2 = (tid & 1) * 2;   // A: 128 rows, 2 segs/thr (x hi/lo)
    int brow = tid >> 1, bseg2 = (tid & 1) * 2;   // B: 128 rows, 2 segs/thr (x hi/lo)

    auto load_chunk = [&](int ch, int s) {
        int k0 = ch * 32;
        const __nv_bfloat16* fH = g_featH + (size_t)(m0 + arow) * 1024 + k0 + aseg2 * 8;
        const __nv_bfloat16* fL = g_featL + (size_t)(m0 + arow) * 1024 + k0 + aseg2 * 8;
        uint32_t daH = sb + GB_AH(s) + arow * RS + aseg2 * 16;
        uint32_t daL = sb + GB_AL(s) + arow * RS + aseg2 * 16;
        CPA16(daH, fH);      CPA16(daH + 16, fH + 8);
        CPA16(daL, fL);      CPA16(daL + 16, fL + 8);
        const __nv_bfloat16* wH = g_wihH + (size_t)(c0b + brow) * 1024 + k0 + bseg2 * 8;
        const __nv_bfloat16* wL = g_wihL + (size_t)(c0b + brow) * 1024 + k0 + bseg2 * 8;
        uint32_t dbH = sb + GB_BH(s) + brow * RS + bseg2 * 16;
        uint32_t dbL = sb + GB_BL(s) + brow * RS + bseg2 * 16;
        CPA16(dbH, wH);      CPA16(dbH + 16, wH + 8);
        CPA16(dbL, wL);      CPA16(dbL + 16, wL + 8);
    };

    const int NC = 32;
    load_chunk(0, 0);
    asm volatile("cp.async.commit_group;");

    for (int ch = 0; ch < NC; ch++) {
        int buf = ch & 1;
        if (ch + 1 < NC) {
            load_chunk(ch + 1, buf ^ 1);
            asm volatile("cp.async.commit_group;");
            asm volatile("cp.async.wait_group 1;");
        } else {
            asm volatile("cp.async.wait_group 0;");
        }
        __syncthreads();

        uint32_t aBh = sb + GB_AH(buf) + (warp_m + aRow) * RS + aKb;
        uint32_t aBl = sb + GB_AL(buf) + (warp_m + aRow) * RS + aKb;
        uint32_t bBh = sb + GB_BH(buf) + (warp_n + bN) * RS + bKb;
        uint32_t bBl = sb + GB_BL(buf) + (warp_n + bN) * RS + bKb;

        #pragma unroll
        for (int ks = 0; ks < 2; ks++) {
            uint32_t ah[2][4], bb[4][4], xx[2][4];
            // phase 1: HH = Ah x Bh
            #pragma unroll
            for (int mt = 0; mt < 2; mt++)
                ldsm4(ah[mt], aBh + mt * 16 * RS + ks * 32);
            #pragma unroll
            for (int nt = 0; nt < 4; nt++)
                ldsm4(bb[nt], bBh + nt * 16 * RS + ks * 32);
            #pragma unroll
            for (int mt = 0; mt < 2; mt++)
                #pragma unroll
                for (int nt = 0; nt < 4; nt++)
                    #pragma unroll
                    for (int f = 0; f < 2; f++)
                        mma16816(acc[mt][nt * 2 + f], ah[mt], &bb[nt][f * 2]);
            // phase 2: LH = Al x Bh (bb still holds Bh)
            #pragma unroll
            for (int mt = 0; mt < 2; mt++)
                ldsm4(xx[mt], aBl + mt * 16 * RS + ks * 32);
            #pragma unroll
            for (int mt = 0; mt < 2; mt++)
                #pragma unroll
                for (int nt = 0; nt < 4; nt++)
                    #pragma unroll
                    for (int f = 0; f < 2; f++)
                        mma16816(acc[mt][nt * 2 + f], xx[mt], &bb[nt][f * 2]);
            // phase 3: HL = Ah x Bl (overwrite bb with Bl)
            #pragma unroll
            for (int nt = 0; nt < 4; nt++)
                ldsm4(bb[nt], bBl + nt * 16 * RS + ks * 32);
            #pragma unroll
            for (int mt = 0; mt < 2; mt++)
                #pragma unroll
                for (int nt = 0; nt < 4; nt++)
                    #pragma unroll
                    for (int f = 0; f < 2; f++)
                        mma16816(acc[mt][nt * 2 + f], ah[mt], &bb[nt][f * 2]);
        }
        __syncthreads();
    }

    int r0 = lane >> 2, cpair = (lane & 3) * 2;
    #pragma unroll
    for (int mt = 0; mt < 2; mt++) {
        #pragma unroll
        for (int nt = 0; nt < 4; nt++)
            #pragma unroll
            for (int f = 0; f < 2; f++) {
                int colL = warp_n + nt * 16 + f * 8 + cpair;
                int col = c0b + colL;
                float b0 = biasS[colL], b1 = biasS[colL + 1];
                int m = m0 + warp_m + mt * 16 + r0;
                float* a = acc[mt][nt * 2 + f];
                float2 v0 = make_float2(a[0] + b0, a[1] + b1);
                float2 v1 = make_float2(a[2] + b0, a[3] + b1);
                *(float2*)&g_gatex[(size_t)m * 512 + col] = v0;
                *(float2*)&g_gatex[(size_t)(m + 8) * 512 + col] = v1;
            }
    }
}

// ============================================================
// Kernel 3: persistent LSTM scan, 512 threads, split-K halves,
// with actor/critic heads fused (per-step warp-per-output dot).
// ============================================================
#define KSW 105
#define KSPLIT 64
// floats: Ws 105*512 | hs 256 | cs 256 | gs 1024 | ps 1024 | Whead 1024 | Bh8 8 | hb 256
#define SCAN_SMEM_FLOATS (KSW * 512 + 256 + 256 + 1024 + 1024 + 1024 + 8 + 256)

__global__ void __launch_bounds__(512, 1)
k_scan(const float* __restrict__ done,
       const float* __restrict__ h0,
       const float* __restrict__ c0,
       const float* __restrict__ aw, const float* __restrict__ ab,
       const float* __restrict__ cw, const float* __restrict__ cb,
       float* __restrict__ dout) {
    extern __shared__ float sm[];
    float* Ws    = sm;                       // [KSW][512]
    float* hs    = sm + KSW * 512;           // [2][128] (masked h)
    float* cs    = hs + 256;                 // [2][128]
    float* gs    = cs + 256;                 // [2][512]
    float4* ps   = (float4*)(gs + 1024);     // [256] partials
    float* Whead = gs + 2048;                // [8][128]
    float* Bh8   = Whead + 1024;             // [8]
    float* hb    = Bh8 + 8;                  // [2][128] (raw h)

    int tid = threadIdx.x;
    int tid2 = tid & 255;
    int half = tid >> 8;
    int lane = tid & 31;
    int e0 = blockIdx.x * 2;

    for (int i = tid; i < KSW * 512; i += 512) Ws[i] = g_whhT[i];
    for (int i = tid; i < 896; i += 512) Whead[i] = aw[i];
    if (tid < 128) Whead[896 + tid] = cw[tid];
    if (tid < 7)  Bh8[tid] = ab[tid];
    if (tid == 7) Bh8[7] = cb[0];
    if (tid < 256) {
        int e = tid >> 7, m = tid & 127;
        int env = e0 + e;
        float s = 1.f - done[env];
        hs[tid] = h0[env * HID + m] * s;
        cs[tid] = c0[env * HID + m] * s;
    }
    __syncthreads();

    int j0 = tid2 * 2;
    int gtype = tid2 >> 6;
    int wo = tid >> 5;                // 16 warps
    int ho = wo & 7, he = wo >> 3;    // head output / env

    for (int t = 0; t < T_STEPS; t++) {
        if (half == 0) {
            const float* gxa = g_gatex + (size_t)(t * B_ENV + e0) * NG;
            const float* gxb = gxa + NG;
            float2 a0 = *(const float2*)&gxa[j0];
            float2 b0 = *(const float2*)&gxb[j0];
            float acc00 = a0.x, acc01 = a0.y;
            float acc10 = b0.x, acc11 = b0.y;
            const float* wp = Ws + j0;
            #pragma unroll 8
            for (int k = 0; k < KSPLIT; k++) {
                float2 w = *(const float2*)wp;
                float ha = hs[k];
                float hb2 = hs[128 + k];
                acc00 += w.x * ha; acc01 += w.y * ha;
                acc10 += w.x * hb2; acc11 += w.y * hb2;
                wp += 512;
            }
            __syncthreads();
            float4 p = ps[tid2];
            acc00 += p.x; acc01 += p.y; acc10 += p.z; acc11 += p.w;
            if (gtype == 2) {
                acc00 = tanhf(acc00); acc01 = tanhf(acc01);
                acc10 = tanhf(acc10); acc11 = tanhf(acc11);
            } else {
                acc00 = 1.f / (1.f + __expf(-acc00));
                acc01 = 1.f / (1.f + __expf(-acc01));
                acc10 = 1.f / (1.f + __expf(-acc10));
                acc11 = 1.f / (1.f + __expf(-acc11));
            }
            gs[j0] = acc00;       gs[j0 + 1] = acc01;
            gs[512 + j0] = acc10; gs[512 + j0 + 1] = acc11;
        } else {
            float acc00 = 0.f, acc01 = 0.f, acc10 = 0.f, acc11 = 0.f;
            const float* wp = Ws + KSPLIT * 512 + j0;
            #pragma unroll 8
            for (int k = KSPLIT; k < KSW; k++) {
                float2 w = *(const float2*)wp;
                float ha = hs[k];
                float hb2 = hs[128 + k];
                acc00 += w.x * ha; acc01 += w.y * ha;
                acc10 += w.x * hb2; acc11 += w.y * hb2;
                wp += 512;
            }
            const float* wg = g_whhT + KSW * 512 + j0;
            #pragma unroll
            for (int k = KSW; k < HID; k++) {
                float2 w = __ldg((const float2*)wg);
                float ha = hs[k];
                float hb2 = hs[128 + k];
                acc00 += w.x * ha; acc01 += w.y * ha;
                acc10 += w.x * hb2; acc11 += w.y * hb2;
                wg += 512;
            }
            ps[tid2] = make_float4(acc00, acc01, acc10, acc11);
            __syncthreads();
        }
        __syncthreads();
        if (tid < 256) {
            int e = tid >> 7, m = tid & 127, env = e0 + e;
            const float* G = gs + e * 512;
            float c = G[128 + m] * cs[tid] + G[m] * G[256 + m];
            float h = G[384 + m] * tanhf(c);
            hb[tid] = h;
            if (t < T_STEPS - 1) {
                float s = 1.f - done[(t + 1) * B_ENV + env];
                hs[tid] = h * s;
                cs[tid] = c * s;
            } else {
                hs[tid] = h;
                cs[tid] = c;
            }
        }
        __syncthreads();
        // ---- fused heads: warp wo computes output ho for env he ----
        {
            const float* hp = hb + he * 128;
            const float* wp2 = Whead + ho * 128;
            float s = hp[lane] * wp2[lane]
                    + hp[lane + 32] * wp2[lane + 32]
                    + hp[lane + 64] * wp2[lane + 64]
                    + hp[lane + 96] * wp2[lane + 96];
            #pragma unroll
            for (int off = 16; off > 0; off >>= 1)
                s += __shfl_xor_sync(0xFFFFFFFFu, s, off);
            if (lane == 0)
                dout[(size_t)(t * B_ENV + e0 + he) * 8 + ho] = s + Bh8[ho];
        }
    }

    if (tid < 256) {
        int e = tid >> 7, m = tid & 127, env = e0 + e;
        dout[262144 + env * HID + m]         = hs[tid];
        dout[262144 + 32768 + env * HID + m] = cs[tid];
    }
}

// ============================================================
extern "C" void kernel_launch(void* const* d_in, const int* in_sizes, int n_in,
                              void* d_out, int out_size) {
    const float* obs  = (const float*)d_in[0];
    const float* done = (const float*)d_in[1];
    const float* h0   = (const float*)d_in[2];
    const float* c0   = (const float*)d_in[3];
    const float* w1   = (const float*)d_in[4];
    const float* b1   = (const float*)d_in[5];
    const float* w2   = (const float*)d_in[6];
    const float* b2   = (const float*)d_in[7];
    const float* w3   = (const float*)d_in[8];
    const float* b3   = (const float*)d_in[9];
    const float* wih  = (const float*)d_in[10];
    const float* whh  = (const float*)d_in[11];
    const float* bih  = (const float*)d_in[12];
    const float* bhh  = (const float*)d_in[13];
    const float* aw   = (const float*)d_in[14];
    const float* ab   = (const float*)d_in[15];
    const float* cw   = (const float*)d_in[16];
    const float* cb   = (const float*)d_in[17];
    float* out = (float*)d_out;

    cudaFuncSetAttribute(k_conv, cudaFuncAttributeMaxDynamicSharedMemorySize,
                         (CONV_WSM + 8 * CONV_PW) * 4);
    cudaFuncSetAttribute(k_scan, cudaFuncAttributeMaxDynamicSharedMemorySize,
                         SCAN_SMEM_FLOATS * 4);
    cudaFuncSetAttribute(k_gemm_mma, cudaFuncAttributeMaxDynamicSharedMemorySize,
                         GB_TOT);

    k_transpose_whh<<<256, 256>>>(whh);
    k_split_wih<<<2048, 256>>>(wih);
    k_conv<<<4096, 256, (CONV_WSM + 8 * CONV_PW) * 4>>>(obs, w1, b1, w2, b2, w3, b3);
    dim3 gg(4, 256);
    k_gemm_mma<<<gg, 256, GB_TOT>>>(bih, bhh);
    k_scan<<<128, 512, SCAN_SMEM_FLOATS * 4>>>(done, h0, c0, aw, ab, cw, cb, out);
}

// round 14
// speedup vs baseline: 1.5798x; 1.4111x over previous
#include <cuda_runtime.h>
#include <cuda_bf16.h>
#include <math.h>
#include <stdint.h>

#define T_STEPS 128
#define B_ENV   256
#define N_TOT   (T_STEPS * B_ENV)   // 32768
#define HID     128
#define NFLAT   1024
#define NG      512                  // 4*HID

// -------- scratch (static device arrays; no allocation) --------
__device__ float g_gatex[N_TOT * NG];            // 64 MB
__device__ float g_whhT [HID * NG];              // 256 KB
__device__ __nv_bfloat16 g_featH[N_TOT * NFLAT]; // 64 MB
__device__ __nv_bfloat16 g_featL[N_TOT * NFLAT]; // 64 MB
__device__ __nv_bfloat16 g_wihH [NG * NFLAT];    // 1 MB
__device__ __nv_bfloat16 g_wihL [NG * NFLAT];    // 1 MB
// packed conv3 weights: [tap][co][ci] rows padded to 40 bf16 (80 B)
__device__ __align__(16) __nv_bfloat16 g_w3pH[4 * 64 * 40];
__device__ __align__(16) __nv_bfloat16 g_w3pL[4 * 64 * 40];

// ================= helpers =================
__device__ __forceinline__ uint32_t s2u(const void* p) {
    uint32_t a;
    asm("{ .reg .u64 t; cvta.to.shared.u64 t, %1; cvt.u32.u64 %0, t; }"
        : "=r"(a) : "l"(p));
    return a;
}
__device__ __forceinline__ void ldsm4(uint32_t* r, uint32_t addr) {
    asm volatile("ldmatrix.sync.aligned.m8n8.x4.shared.b16 {%0,%1,%2,%3}, [%4];"
                 : "=r"(r[0]), "=r"(r[1]), "=r"(r[2]), "=r"(r[3]) : "r"(addr));
}
__device__ __forceinline__ void mma16816(float* d, const uint32_t* a, const uint32_t* b) {
    asm volatile(
        "mma.sync.aligned.m16n8k16.row.col.f32.bf16.bf16.f32 "
        "{%0,%1,%2,%3}, {%4,%5,%6,%7}, {%8,%9}, {%0,%1,%2,%3};"
        : "+f"(d[0]), "+f"(d[1]), "+f"(d[2]), "+f"(d[3])
        : "r"(a[0]), "r"(a[1]), "r"(a[2]), "r"(a[3]), "r"(b[0]), "r"(b[1]));
}
#define CPA16(dst, src) \
    asm volatile("cp.async.cg.shared.global [%0], [%1], 16;" :: "r"(dst), "l"(src))

// ============================================================
// Kernel 0a: transpose w_hh [512,128] -> w_hhT [128,512]
// ============================================================
__global__ void k_transpose_whh(const float* __restrict__ whh) {
    int idx = blockIdx.x * blockDim.x + threadIdx.x;
    if (idx < NG * HID) {
        int k = idx >> 9;
        int j = idx & 511;
        g_whhT[idx] = whh[j * HID + k];
    }
}

// ============================================================
// Kernel 0b: split w_ih into bf16 hi/lo
// ============================================================
__global__ void k_split_wih(const float* __restrict__ wih) {
    int idx = blockIdx.x * blockDim.x + threadIdx.x;
    if (idx < NG * NFLAT) {
        float v = wih[idx];
        __nv_bfloat16 h = __float2bfloat16(v);
        g_wihH[idx] = h;
        g_wihL[idx] = __float2bfloat16(v - __bfloat162float(h));
    }
}

// ============================================================
// Kernel 0c: pack w3 [64,32,2,2] -> [tap][co][ci] bf16 hi/lo, rows padded 80B
// ============================================================
__global__ void k_pack_w3(const float* __restrict__ w3) {
    int idx = blockIdx.x * blockDim.x + threadIdx.x;   // 8192
    if (idx < 4 * 64 * 32) {
        int t  = idx >> 11;
        int co = (idx >> 5) & 63;
        int ci = idx & 31;
        float v = w3[(co * 32 + ci) * 4 + t];
        __nv_bfloat16 h = __float2bfloat16(v);
        g_w3pH[(t * 64 + co) * 40 + ci] = h;
        g_w3pL[(t * 64 + co) * 40 + ci] = __float2bfloat16(v - __bfloat162float(h));
    }
}

// ============================================================
// Kernel 1: conv stack. conv1/conv2 scalar register-blocked,
// conv3 = implicit-GEMM on tensor pipe (3-product split bf16,
// per-lane-row ldmatrix over position-major X2 tiles, no im2col).
// ============================================================
// block-shared float offsets:
//   W1 0(192) B1 192(16) W2 208(2048) B2 2256(32) B3 2288(64)
//   W3H 2352(5120) W3L 7472(5120) -> per-warp base 12592
#define CONV_WSM 12592
#define CONV_PW  1724   // O 147 | X1 @148(576) | X2tH @724(500) | X2tL @1224(500)

__global__ void __launch_bounds__(256)
k_conv(const float* __restrict__ obs,
       const float* __restrict__ w1, const float* __restrict__ b1,
       const float* __restrict__ w2, const float* __restrict__ b2,
       const float* __restrict__ b3) {
    extern __shared__ float sm[];
    float* W1 = sm;
    float* B1 = sm + 192;
    float* W2 = sm + 208;
    float* B2 = sm + 2256;
    float* B3 = sm + 2288;
    int tid = threadIdx.x;
    for (int i = tid; i < 192;  i += 256) W1[i] = w1[i];
    for (int i = tid; i < 16;   i += 256) B1[i] = b1[i];
    for (int i = tid; i < 2048; i += 256) W2[i] = w2[i];
    for (int i = tid; i < 32;   i += 256) B2[i] = b2[i];
    for (int i = tid; i < 64;   i += 256) B3[i] = b3[i];
    {   // packed conv3 weights (20480 B each), vectorized
        uint4* dH = (uint4*)(sm + 2352);
        uint4* dL = (uint4*)(sm + 7472);
        const uint4* gH = (const uint4*)g_w3pH;
        const uint4* gL = (const uint4*)g_w3pL;
        for (int i = tid; i < 1280; i += 256) { dH[i] = gH[i]; dL[i] = gL[i]; }
    }
    __syncthreads();

    int warp = tid >> 5, lane = tid & 31;
    int n = blockIdx.x * 8 + warp;
    float* buf = sm + CONV_WSM + warp * CONV_PW;
    float* O  = buf;          // obs [7][7][3] HWC
    float* X1 = buf + 148;    // [16][6][6] fp32
    char*  X2tH = (char*)(buf + 724);   // [25 pos][32 ci] bf16, 80 B rows
    char*  X2tL = (char*)(buf + 1224);

    const float* op = obs + (size_t)n * 147;
    for (int i = lane; i < 147; i += 32) O[i] = op[i];
    __syncwarp();

    // ---- conv1: lane = (ch, row-half) ----
    {
        int ch = lane >> 1, half = lane & 1, y0 = half * 3;
        float acc[3][6];
        float bv = B1[ch];
        #pragma unroll
        for (int r = 0; r < 3; r++)
            #pragma unroll
            for (int x = 0; x < 6; x++) acc[r][x] = bv;
        for (int ci = 0; ci < 3; ci++) {
            const float* w = W1 + ch * 12 + ci * 4;
            float w0 = w[0], w1v = w[1], w2v = w[2], w3v = w[3];
            float in[4][7];
            #pragma unroll
            for (int r = 0; r < 4; r++)
                #pragma unroll
                for (int x = 0; x < 7; x++)
                    in[r][x] = O[((y0 + r) * 7 + x) * 3 + ci];
            #pragma unroll
            for (int r = 0; r < 3; r++)
                #pragma unroll
                for (int x = 0; x < 6; x++)
                    acc[r][x] += in[r][x] * w0 + in[r][x + 1] * w1v
                               + in[r + 1][x] * w2v + in[r + 1][x + 1] * w3v;
        }
        #pragma unroll
        for (int r = 0; r < 3; r++)
            #pragma unroll
            for (int x = 0; x < 6; x++)
                X1[ch * 36 + (y0 + r) * 6 + x] = fmaxf(acc[r][x], 0.f);
    }
    __syncwarp();

    // ---- conv2: lane = ch; write POSITION-MAJOR bf16 hi/lo tiles ----
    {
        int ch = lane;
        float acc[5][5];
        float bv = B2[ch];
        #pragma unroll
        for (int y = 0; y < 5; y++)
            #pragma unroll
            for (int x = 0; x < 5; x++) acc[y][x] = bv;
        for (int ci = 0; ci < 16; ci++) {
            const float* w = W2 + ch * 64 + ci * 4;
            float w0 = w[0], w1v = w[1], w2v = w[2], w3v = w[3];
            float in[6][6];
            const float* xp = X1 + ci * 36;
            #pragma unroll
            for (int y = 0; y < 6; y++)
                #pragma unroll
                for (int x = 0; x < 6; x++) in[y][x] = xp[y * 6 + x];
            #pragma unroll
            for (int y = 0; y < 5; y++)
                #pragma unroll
                for (int x = 0; x < 5; x++)
                    acc[y][x] += in[y][x] * w0 + in[y][x + 1] * w1v
                               + in[y + 1][x] * w2v + in[y + 1][x + 1] * w3v;
        }
        #pragma unroll
        for (int y = 0; y < 5; y++)
            #pragma unroll
            for (int x = 0; x < 5; x++) {
                float v = fmaxf(acc[y][x], 0.f);
                __nv_bfloat16 h = __float2bfloat16(v);
                int p = y * 5 + x;
                *(__nv_bfloat16*)(X2tH + p * 80 + ch * 2) = h;
                *(__nv_bfloat16*)(X2tL + p * 80 + ch * 2) =
                    __float2bfloat16(v - __bfloat162float(h));
            }
    }
    __syncwarp();

    // ---- conv3: implicit GEMM, D[16 pos,64 co], 4 taps x K32, split 3-product ----
    {
        uint32_t XbH = s2u(X2tH);
        uint32_t XbL = s2u(X2tL);
        uint32_t WbH = s2u(sm + 2352);
        uint32_t WbL = s2u(sm + 7472);
        int r = lane & 15;
        int py = r >> 2, px = r & 3;
        int khalf = lane >> 4;
        int bN = (lane & 7) + ((lane >> 4) << 3);
        int bKb = ((lane >> 3) & 1) * 16;

        float acc[8][4];
        #pragma unroll
        for (int i = 0; i < 8; i++)
            #pragma unroll
            for (int q = 0; q < 4; q++) acc[i][q] = 0.f;

        #pragma unroll
        for (int t = 0; t < 4; t++) {
            int dy = t >> 1, dx = t & 1;
            uint32_t arow = (uint32_t)((((py + dy) * 5) + px + dx) * 80);
            uint32_t btap = (uint32_t)(t * 5120 + bN * 80 + bKb);
            #pragma unroll
            for (int ks = 0; ks < 2; ks++) {
                uint32_t aoff = arow + ks * 32 + khalf * 16;
                uint32_t ah[4], al[4];
                ldsm4(ah, XbH + aoff);
                ldsm4(al, XbL + aoff);
                #pragma unroll
                for (int ng = 0; ng < 4; ng++) {
                    uint32_t bh[4], bl[4];
                    uint32_t baddr = btap + ng * 1280 + ks * 32;
                    ldsm4(bh, WbH + baddr);
                    ldsm4(bl, WbL + baddr);
                    #pragma unroll
                    for (int f = 0; f < 2; f++) {
                        float* d = acc[ng * 2 + f];
                        mma16816(d, ah, &bh[f * 2]);
                        mma16816(d, ah, &bl[f * 2]);
                        mma16816(d, al, &bh[f * 2]);
                    }
                }
            }
        }

        // epilogue: bias + relu + hi/lo split, feat idx = co*16 + pos
        int r0 = lane >> 2, cpair = (lane & 3) * 2;
        __nv_bfloat16* fh = g_featH + (size_t)n * NFLAT;
        __nv_bfloat16* fl = g_featL + (size_t)n * NFLAT;
        #pragma unroll
        for (int ng = 0; ng < 4; ng++)
            #pragma unroll
            for (int f = 0; f < 2; f++) {
                float* d = acc[ng * 2 + f];
                int co0 = ng * 16 + f * 8 + cpair;
                #pragma unroll
                for (int q = 0; q < 2; q++) {
                    int co = co0 + q;
                    float bv = B3[co];
                    float v0 = fmaxf(d[q] + bv, 0.f);        // pos r0
                    float v1 = fmaxf(d[2 + q] + bv, 0.f);    // pos r0+8
                    __nv_bfloat16 h0 = __float2bfloat16(v0);
                    __nv_bfloat16 h1 = __float2bfloat16(v1);
                    fh[co * 16 + r0]     = h0;
                    fh[co * 16 + r0 + 8] = h1;
                    fl[co * 16 + r0]     = __float2bfloat16(v0 - __bfloat162float(h0));
                    fl[co * 16 + r0 + 8] = __float2bfloat16(v1 - __bfloat162float(h1));
                }
            }
    }
}

// ============================================================
// Kernel 2: 3-product split-bf16 GEMM via mma.sync (R11 proven).
// BM=128, BN=128, BK=32, warp tile 32x64, sequenced products.
// ============================================================
#define RS 80
#define GB_STAGE 40960
#define GB_AH(s) (512 + (s) * GB_STAGE)
#define GB_AL(s) (GB_AH(s) + 10240)
#define GB_BH(s) (GB_AH(s) + 20480)
#define GB_BL(s) (GB_AH(s) + 30720)
#define GB_TOT (512 + 2 * GB_STAGE)  // 82432 bytes

__global__ void __launch_bounds__(256, 2)
k_gemm_mma(const float* __restrict__ bih, const float* __restrict__ bhh) {
    extern __shared__ char smc[];
    uint32_t sb = s2u(smc);
    float* biasS = (float*)smc;
    int tid = threadIdx.x, wid = tid >> 5, lane = tid & 31;
    int m0 = blockIdx.y * 128, c0b = blockIdx.x * 128;
    int warp_m = (wid & 3) * 32, warp_n = (wid >> 2) * 64;

    for (int i = tid; i < 128; i += 256) biasS[i] = bih[c0b + i] + bhh[c0b + i];

    int aRow = lane & 15;
    int aKb  = (lane >> 4) * 16;
    int bN   = (lane & 7) + ((lane >> 4) << 3);
    int bKb  = ((lane >> 3) & 1) * 16;

    float acc[2][8][4];
    #pragma unroll
    for (int i = 0; i < 2; i++)
        #pragma unroll
        for (int j = 0; j < 8; j++)
            #pragma unroll
            for (int q = 0; q < 4; q++) acc[i][j][q] = 0.f;

    int arow = tid >> 1, aseg2 = (tid & 1) * 2;
    int brow = tid >> 1, bseg2 = (tid & 1) * 2;

    auto load_chunk = [&](int ch, int s) {
        int k0 = ch * 32;
        const __nv_bfloat16* fH = g_featH + (size_t)(m0 + arow) * 1024 + k0 + aseg2 * 8;
        const __nv_bfloat16* fL = g_featL + (size_t)(m0 + arow) * 1024 + k0 + aseg2 * 8;
        uint32_t daH = sb + GB_AH(s) + arow * RS + aseg2 * 16;
        uint32_t daL = sb + GB_AL(s) + arow * RS + aseg2 * 16;
        CPA16(daH, fH);      CPA16(daH + 16, fH + 8);
        CPA16(daL, fL);      CPA16(daL + 16, fL + 8);
        const __nv_bfloat16* wH = g_wihH + (size_t)(c0b + brow) * 1024 + k0 + bseg2 * 8;
        const __nv_bfloat16* wL = g_wihL + (size_t)(c0b + brow) * 1024 + k0 + bseg2 * 8;
        uint32_t dbH = sb + GB_BH(s) + brow * RS + bseg2 * 16;
        uint32_t dbL = sb + GB_BL(s) + brow * RS + bseg2 * 16;
        CPA16(dbH, wH);      CPA16(dbH + 16, wH + 8);
        CPA16(dbL, wL);      CPA16(dbL + 16, wL + 8);
    };

    const int NC = 32;
    load_chunk(0, 0);
    asm volatile("cp.async.commit_group;");

    for (int ch = 0; ch < NC; ch++) {
        int buf = ch & 1;
        if (ch + 1 < NC) {
            load_chunk(ch + 1, buf ^ 1);
            asm volatile("cp.async.commit_group;");
            asm volatile("cp.async.wait_group 1;");
        } else {
            asm volatile("cp.async.wait_group 0;");
        }
        __syncthreads();

        uint32_t aBh = sb + GB_AH(buf) + (warp_m + aRow) * RS + aKb;
        uint32_t aBl = sb + GB_AL(buf) + (warp_m + aRow) * RS + aKb;
        uint32_t bBh = sb + GB_BH(buf) + (warp_n + bN) * RS + bKb;
        uint32_t bBl = sb + GB_BL(buf) + (warp_n + bN) * RS + bKb;

        #pragma unroll
        for (int ks = 0; ks < 2; ks++) {
            uint32_t ah[2][4], bb[4][4], xx[2][4];
            #pragma unroll
            for (int mt = 0; mt < 2; mt++)
                ldsm4(ah[mt], aBh + mt * 16 * RS + ks * 32);
            #pragma unroll
            for (int nt = 0; nt < 4; nt++)
                ldsm4(bb[nt], bBh + nt * 16 * RS + ks * 32);
            #pragma unroll
            for (int mt = 0; mt < 2; mt++)
                #pragma unroll
                for (int nt = 0; nt < 4; nt++)
                    #pragma unroll
                    for (int f = 0; f < 2; f++)
                        mma16816(acc[mt][nt * 2 + f], ah[mt], &bb[nt][f * 2]);
            #pragma unroll
            for (int mt = 0; mt < 2; mt++)
                ldsm4(xx[mt], aBl + mt * 16 * RS + ks * 32);
            #pragma unroll
            for (int mt = 0; mt < 2; mt++)
                #pragma unroll
                for (int nt = 0; nt < 4; nt++)
                    #pragma unroll
                    for (int f = 0; f < 2; f++)
                        mma16816(acc[mt][nt * 2 + f], xx[mt], &bb[nt][f * 2]);
            #pragma unroll
            for (int nt = 0; nt < 4; nt++)
                ldsm4(bb[nt], bBl + nt * 16 * RS + ks * 32);
            #pragma unroll
            for (int mt = 0; mt < 2; mt++)
                #pragma unroll
                for (int nt = 0; nt < 4; nt++)
                    #pragma unroll
                    for (int f = 0; f < 2; f++)
                        mma16816(acc[mt][nt * 2 + f], ah[mt], &bb[nt][f * 2]);
        }
        __syncthreads();
    }

    int r0 = lane >> 2, cpair = (lane & 3) * 2;
    #pragma unroll
    for (int mt = 0; mt < 2; mt++) {
        #pragma unroll
        for (int nt = 0; nt < 4; nt++)
            #pragma unroll
            for (int f = 0; f < 2; f++) {
                int colL = warp_n + nt * 16 + f * 8 + cpair;
                int col = c0b + colL;
                float b0 = biasS[colL], b1 = biasS[colL + 1];
                int m = m0 + warp_m + mt * 16 + r0;
                float* a = acc[mt][nt * 2 + f];
                float2 v0 = make_float2(a[0] + b0, a[1] + b1);
                float2 v1 = make_float2(a[2] + b0, a[3] + b1);
                *(float2*)&g_gatex[(size_t)m * 512 + col] = v0;
                *(float2*)&g_gatex[(size_t)(m + 8) * 512 + col] = v1;
            }
    }
}

// ============================================================
// Kernel 3: persistent LSTM scan + fused heads (R11 proven).
// ============================================================
#define KSW 105
#define KSPLIT 64
#define SCAN_SMEM_FLOATS (KSW * 512 + 256 + 256 + 1024 + 1024 + 1024 + 8 + 256)

__global__ void __launch_bounds__(512, 1)
k_scan(const float* __restrict__ done,
       const float* __restrict__ h0,
       const float* __restrict__ c0,
       const float* __restrict__ aw, const float* __restrict__ ab,
       const float* __restrict__ cw, const float* __restrict__ cb,
       float* __restrict__ dout) {
    extern __shared__ float sm[];
    float* Ws    = sm;
    float* hs    = sm + KSW * 512;
    float* cs    = hs + 256;
    float* gs    = cs + 256;
    float4* ps   = (float4*)(gs + 1024);
    float* Whead = gs + 2048;
    float* Bh8   = Whead + 1024;
    float* hb    = Bh8 + 8;

    int tid = threadIdx.x;
    int tid2 = tid & 255;
    int half = tid >> 8;
    int lane = tid & 31;
    int e0 = blockIdx.x * 2;

    for (int i = tid; i < KSW * 512; i += 512) Ws[i] = g_whhT[i];
    for (int i = tid; i < 896; i += 512) Whead[i] = aw[i];
    if (tid < 128) Whead[896 + tid] = cw[tid];
    if (tid < 7)  Bh8[tid] = ab[tid];
    if (tid == 7) Bh8[7] = cb[0];
    if (tid < 256) {
        int e = tid >> 7, m = tid & 127;
        int env = e0 + e;
        float s = 1.f - done[env];
        hs[tid] = h0[env * HID + m] * s;
        cs[tid] = c0[env * HID + m] * s;
    }
    __syncthreads();

    int j0 = tid2 * 2;
    int gtype = tid2 >> 6;
    int wo = tid >> 5;
    int ho = wo & 7, he = wo >> 3;

    for (int t = 0; t < T_STEPS; t++) {
        if (half == 0) {
            const float* gxa = g_gatex + (size_t)(t * B_ENV + e0) * NG;
            const float* gxb = gxa + NG;
            float2 a0 = *(const float2*)&gxa[j0];
            float2 b0 = *(const float2*)&gxb[j0];
            float acc00 = a0.x, acc01 = a0.y;
            float acc10 = b0.x, acc11 = b0.y;
            const float* wp = Ws + j0;
            #pragma unroll 8
            for (int k = 0; k < KSPLIT; k++) {
                float2 w = *(const float2*)wp;
                float ha = hs[k];
                float hb2 = hs[128 + k];
                acc00 += w.x * ha; acc01 += w.y * ha;
                acc10 += w.x * hb2; acc11 += w.y * hb2;
                wp += 512;
            }
            __syncthreads();
            float4 p = ps[tid2];
            acc00 += p.x; acc01 += p.y; acc10 += p.z; acc11 += p.w;
            if (gtype == 2) {
                acc00 = tanhf(acc00); acc01 = tanhf(acc01);
                acc10 = tanhf(acc10); acc11 = tanhf(acc11);
            } else {
                acc00 = 1.f / (1.f + __expf(-acc00));
                acc01 = 1.f / (1.f + __expf(-acc01));
                acc10 = 1.f / (1.f + __expf(-acc10));
                acc11 = 1.f / (1.f + __expf(-acc11));
            }
            gs[j0] = acc00;       gs[j0 + 1] = acc01;
            gs[512 + j0] = acc10; gs[512 + j0 + 1] = acc11;
        } else {
            float acc00 = 0.f, acc01 = 0.f, acc10 = 0.f, acc11 = 0.f;
            const float* wp = Ws + KSPLIT * 512 + j0;
            #pragma unroll 8
            for (int k = KSPLIT; k < KSW; k++) {
                float2 w = *(const float2*)wp;
                float ha = hs[k];
                float hb2 = hs[128 + k];
                acc00 += w.x * ha; acc01 += w.y * ha;
                acc10 += w.x * hb2; acc11 += w.y * hb2;
                wp += 512;
            }
            const float* wg = g_whhT + KSW * 512 + j0;
            #pragma unroll
            for (int k = KSW; k < HID; k++) {
                float2 w = __ldg((const float2*)wg);
                float ha = hs[k];
                float hb2 = hs[128 + k];
                acc00 += w.x * ha; acc01 += w.y * ha;
                acc10 += w.x * hb2; acc11 += w.y * hb2;
                wg += 512;
            }
            ps[tid2] = make_float4(acc00, acc01, acc10, acc11);
            __syncthreads();
        }
        __syncthreads();
        if (tid < 256) {
            int e = tid >> 7, m = tid & 127, env = e0 + e;
            const float* G = gs + e * 512;
            float c = G[128 + m] * cs[tid] + G[m] * G[256 + m];
            float h = G[384 + m] * tanhf(c);
            hb[tid] = h;
            if (t < T_STEPS - 1) {
                float s = 1.f - done[(t + 1) * B_ENV + env];
                hs[tid] = h * s;
                cs[tid] = c * s;
            } else {
                hs[tid] = h;
                cs[tid] = c;
            }
        }
        __syncthreads();
        {
            const float* hp = hb + he * 128;
            const float* wp2 = Whead + ho * 128;
            float s = hp[lane] * wp2[lane]
                    + hp[lane + 32] * wp2[lane + 32]
                    + hp[lane + 64] * wp2[lane + 64]
                    + hp[lane + 96] * wp2[lane + 96];
            #pragma unroll
            for (int off = 16; off > 0; off >>= 1)
                s += __shfl_xor_sync(0xFFFFFFFFu, s, off);
            if (lane == 0)
                dout[(size_t)(t * B_ENV + e0 + he) * 8 + ho] = s + Bh8[ho];
        }
    }

    if (tid < 256) {
        int e = tid >> 7, m = tid & 127, env = e0 + e;
        dout[262144 + env * HID + m]         = hs[tid];
        dout[262144 + 32768 + env * HID + m] = cs[tid];
    }
}

// ============================================================
extern "C" void kernel_launch(void* const* d_in, const int* in_sizes, int n_in,
                              void* d_out, int out_size) {
    const float* obs  = (const float*)d_in[0];
    const float* done = (const float*)d_in[1];
    const float* h0   = (const float*)d_in[2];
    const float* c0   = (const float*)d_in[3];
    const float* w1   = (const float*)d_in[4];
    const float* b1   = (const float*)d_in[5];
    const float* w2   = (const float*)d_in[6];
    const float* b2   = (const float*)d_in[7];
    const float* w3   = (const float*)d_in[8];
    const float* b3   = (const float*)d_in[9];
    const float* wih  = (const float*)d_in[10];
    const float* whh  = (const float*)d_in[11];
    const float* bih  = (const float*)d_in[12];
    const float* bhh  = (const float*)d_in[13];
    const float* aw   = (const float*)d_in[14];
    const float* ab   = (const float*)d_in[15];
    const float* cw   = (const float*)d_in[16];
    const float* cb   = (const float*)d_in[17];
    float* out = (float*)d_out;

    cudaFuncSetAttribute(k_conv, cudaFuncAttributeMaxDynamicSharedMemorySize,
                         (CONV_WSM + 8 * CONV_PW) * 4);
    cudaFuncSetAttribute(k_scan, cudaFuncAttributeMaxDynamicSharedMemorySize,
                         SCAN_SMEM_FLOATS * 4);
    cudaFuncSetAttribute(k_gemm_mma, cudaFuncAttributeMaxDynamicSharedMemorySize,
                         GB_TOT);

    k_transpose_whh<<<256, 256>>>(whh);
    k_split_wih<<<2048, 256>>>(wih);
    k_pack_w3<<<32, 256>>>(w3);
    k_conv<<<4096, 256, (CONV_WSM + 8 * CONV_PW) * 4>>>(obs, w1, b1, w2, b2, b3);
    dim3 gg(4, 256);
    k_gemm_mma<<<gg, 256, GB_TOT>>>(bih, bhh);
    k_scan<<<128, 512, SCAN_SMEM_FLOATS * 4>>>(done, h0, c0, aw, ab, cw, cb, out);
}